// round 12
// baseline (speedup 1.0000x reference)
#include <cuda_runtime.h>
#include <cuda_fp16.h>
#include <math.h>
#include <stdint.h>

#define SQ   2048
#define EM   768
#define NH   12
#define DH   64
#define FFD  3072
#define NL   4
#define EPSF 1e-5f
#define NCHUNK 32

// GEMM tiling: BM=BN=128, BK=64 halves, 256 threads, warp tile 64x32
#define BM 128
#define BN 128
#define BK 64
#define RSTR 36            // smem row stride in u32 (32 used + 4 pad)
#define A_OFF 0
#define BH_OFF 4608
#define BL_OFF 9216
#define STAGE_U32 13824
#define SMEM_BYTES (2*STAGE_U32*4)   // 110592

// weight pool offsets (elements) — Wq,Wk,Wv,W1,W2 (Wo handled via N fusion)
#define WMAT   589824            // 768*768
#define W1MAT  2359296           // 768*3072
#define OFF_WQ 0
#define OFF_WK (4*WMAT)
#define OFF_WV (8*WMAT)
#define OFF_W1 (12*WMAT)
#define OFF_W2 (12*WMAT + 4*W1MAT)
#define WTOTAL (12*WMAT + 8*W1MAT)

// ---------------- scratch (no allocations allowed) ----------------
__device__ float g_x[SQ*EM];                 // residual stream (fp32)
__device__ float g_k[SQ*EM];                 // K (fp32)
__device__ float g_v[SQ*EM];                 // V (fp32)
__device__ float g_Mp[NH*NCHUNK*DH*DH];      // partial K^T V
__device__ float g_part[3*SQ*EM];            // split-K partials
__device__ __half g_qh[SQ*EM];               // Q (fp16)
__device__ __half g_h[SQ*EM];                // LN output (fp16)
__device__ __half g_ff[SQ*FFD];              // MLP hidden (fp16)
__device__ __half gwt_hi[WTOTAL];            // transposed weights hi
__device__ __half gwt_lo[WTOTAL];            // transposed weights lo
__device__ __half g_nh[EM*EM];               // N = scale*M*Wo, transposed, hi
__device__ __half g_nl[EM*EM];               // N lo

// ---------------- helpers ----------------
__device__ __forceinline__ void mma_fp16(float c[4], const uint32_t a[4], const uint32_t b[2]) {
    asm volatile(
        "mma.sync.aligned.m16n8k16.row.col.f32.f16.f16.f32 "
        "{%0,%1,%2,%3},{%4,%5,%6,%7},{%8,%9},{%0,%1,%2,%3};\n"
        : "+f"(c[0]), "+f"(c[1]), "+f"(c[2]), "+f"(c[3])
        : "r"(a[0]), "r"(a[1]), "r"(a[2]), "r"(a[3]), "r"(b[0]), "r"(b[1]));
}
__device__ __forceinline__ void ldsm_x4(uint32_t& r0, uint32_t& r1, uint32_t& r2, uint32_t& r3,
                                        uint32_t addr) {
    asm volatile("ldmatrix.sync.aligned.m8n8.x4.shared.b16 {%0,%1,%2,%3}, [%4];"
                 : "=r"(r0), "=r"(r1), "=r"(r2), "=r"(r3) : "r"(addr));
}
__device__ __forceinline__ void cpa16(uint32_t dst, const void* src) {
    asm volatile("cp.async.cg.shared.global [%0], [%1], 16;\n" :: "r"(dst), "l"(src) : "memory");
}
__device__ __forceinline__ void cp_commit() { asm volatile("cp.async.commit_group;\n" ::: "memory"); }
__device__ __forceinline__ void cp_wait1()  { asm volatile("cp.async.wait_group 1;\n" ::: "memory"); }
__device__ __forceinline__ void cp_wait0()  { asm volatile("cp.async.wait_group 0;\n" ::: "memory"); }

__device__ __forceinline__ void split_fp16(float v, __half& hi, __half& lo) {
    hi = __float2half_rn(v);
    lo = __float2half_rn(v - __half2float(hi));
}

// ---------------- weight transpose + split: src[L][K][N] -> dst[L][N][K] (hi,lo fp16) ----------------
template<bool QKV>
__global__ void wconv_k(const float* __restrict__ s0, const float* __restrict__ s1,
                        const float* __restrict__ s2,
                        __half* __restrict__ dhi, __half* __restrict__ dlo,
                        int K, int N, int poolStride) {
    __shared__ float t[32][33];
    int m = 0, l = blockIdx.z;
    if (QKV) { m = blockIdx.z / NL; l = blockIdx.z % NL; }
    const float* src = (m == 0) ? s0 : (m == 1) ? s1 : s2;
    const size_t lofs = (size_t)l * K * N;
    const size_t dofs = (size_t)m * 4 * WMAT + (size_t)l * poolStride;
    const int n0 = blockIdx.x * 32, k0 = blockIdx.y * 32;
    const int tx = threadIdx.x, ty = threadIdx.y;
    #pragma unroll
    for (int i = 0; i < 4; i++)
        t[ty + 8*i][tx] = src[lofs + (size_t)(k0 + ty + 8*i) * N + n0 + tx];
    __syncthreads();
    const int u = tx & 15, nx = tx >> 4;
    #pragma unroll
    for (int i = 0; i < 2; i++) {
        int n = ty + 8*i + 16*nx;
        float v0 = t[2*u][n], v1 = t[2*u + 1][n];
        __half h0, l0, h1, l1;
        split_fp16(v0, h0, l0);
        split_fp16(v1, h1, l1);
        size_t o = dofs + (size_t)(n0 + n) * K + k0 + 2*u;
        *reinterpret_cast<__half2*>(dhi + o) = __halves2half2(h0, h1);
        *reinterpret_cast<__half2*>(dlo + o) = __halves2half2(l0, l1);
    }
}

// ---------------- initial: x = emb + wpe, then LN -> fp16 ----------------
__global__ void __launch_bounds__(256)
addln_k(const float* __restrict__ emb, const float* __restrict__ wpe,
        float* __restrict__ px, __half* __restrict__ oh,
        const float* __restrict__ g, const float* __restrict__ b) {
    const int row = blockIdx.x;
    float loc[3];
    float s = 0.f, s2 = 0.f;
    #pragma unroll
    for (int t = 0; t < 3; t++) {
        int j = threadIdx.x + t * 256;
        size_t o = (size_t)row * EM + j;
        float v = emb[o] + wpe[o];
        px[o] = v;
        loc[t] = v;
        s += v; s2 += v * v;
    }
    __shared__ float rs[32], rs2[32];
    #pragma unroll
    for (int o = 16; o; o >>= 1) {
        s  += __shfl_down_sync(0xffffffffu, s,  o);
        s2 += __shfl_down_sync(0xffffffffu, s2, o);
    }
    int w = threadIdx.x >> 5, l = threadIdx.x & 31;
    if (l == 0) { rs[w] = s; rs2[w] = s2; }
    __syncthreads();
    if (w == 0) {
        s  = (l < 8) ? rs[l]  : 0.f;
        s2 = (l < 8) ? rs2[l] : 0.f;
        #pragma unroll
        for (int o = 4; o; o >>= 1) {
            s  += __shfl_down_sync(0xffffffffu, s,  o);
            s2 += __shfl_down_sync(0xffffffffu, s2, o);
        }
        if (l == 0) { rs[0] = s; rs2[0] = s2; }
    }
    __syncthreads();
    float mu  = rs[0] * (1.0f / EM);
    float var = rs2[0] * (1.0f / EM) - mu * mu;
    float inv = rsqrtf(var + EPSF);
    #pragma unroll
    for (int t = 0; t < 3; t++) {
        int j = threadIdx.x + t * 256;
        oh[(size_t)row * EM + j] = __float2half_rn((loc[t] - mu) * inv * g[j] + b[j]);
    }
}

// ---------------- combine 3 split-K partials + bias + residual, then LayerNorm ----------------
template<bool HALF>
__global__ void __launch_bounds__(256)
combine_ln_k(const float* __restrict__ parts, const float* __restrict__ bias,
             float* __restrict__ px, float* __restrict__ outf, __half* __restrict__ oh,
             const float* __restrict__ g, const float* __restrict__ b) {
    const int row = blockIdx.x;
    float loc[3];
    float s = 0.f, s2 = 0.f;
    #pragma unroll
    for (int t = 0; t < 3; t++) {
        int j = threadIdx.x + t * 256;
        size_t o = (size_t)row * EM + j;
        float v = px[o] + bias[j] + parts[o] + parts[o + (size_t)SQ*EM] + parts[o + 2*(size_t)SQ*EM];
        px[o] = v;
        loc[t] = v;
        s += v; s2 += v * v;
    }
    __shared__ float rs[32], rs2[32];
    #pragma unroll
    for (int o = 16; o; o >>= 1) {
        s  += __shfl_down_sync(0xffffffffu, s,  o);
        s2 += __shfl_down_sync(0xffffffffu, s2, o);
    }
    int w = threadIdx.x >> 5, l = threadIdx.x & 31;
    if (l == 0) { rs[w] = s; rs2[w] = s2; }
    __syncthreads();
    if (w == 0) {
        s  = (l < 8) ? rs[l]  : 0.f;
        s2 = (l < 8) ? rs2[l] : 0.f;
        #pragma unroll
        for (int o = 4; o; o >>= 1) {
            s  += __shfl_down_sync(0xffffffffu, s,  o);
            s2 += __shfl_down_sync(0xffffffffu, s2, o);
        }
        if (l == 0) { rs[0] = s; rs2[0] = s2; }
    }
    __syncthreads();
    float mu  = rs[0] * (1.0f / EM);
    float var = rs2[0] * (1.0f / EM) - mu * mu;
    float inv = rsqrtf(var + EPSF);
    #pragma unroll
    for (int t = 0; t < 3; t++) {
        int j = threadIdx.x + t * 256;
        float v = (loc[t] - mu) * inv * g[j] + b[j];
        if (HALF) oh[(size_t)row * EM + j] = __float2half_rn(v);
        else      outf[(size_t)row * EM + j] = v;
    }
}

// ---------------- 2-term fp16 tensor-core GEMM body (BK=64, ldmatrix fragments) ----------------
// A (fp16, [M,Kfull] row-major), B (hi/lo fp16, [N,Kfull] k-major)
template<bool GELU, bool RES, bool OHALF, bool PART>
__device__ __forceinline__ void gemm_body(
    const __half* __restrict__ Ah,
    const __half* __restrict__ Bh, const __half* __restrict__ Bl,
    const float* __restrict__ bias, const float* __restrict__ res,
    float* __restrict__ C, __half* __restrict__ Ch,
    int N, int Kfull, int kbase, int kcount, int row0, int col0, uint32_t* smem)
{
    const int tid  = threadIdx.x;
    const int lane = tid & 31, warp = tid >> 5;
    const int wm = warp >> 2, wn = warp & 3;   // 2 x 4 warp grid
    const int g = lane >> 2, q = lane & 3;
    const int lane15 = lane & 15, laneHi = lane >> 4;

    uint32_t sbase = (uint32_t)__cvta_generic_to_shared(smem);

    float acc[4][4][4];
    #pragma unroll
    for (int i = 0; i < 4; i++)
        #pragma unroll
        for (int j = 0; j < 4; j++)
            #pragma unroll
            for (int t = 0; t < 4; t++) acc[i][j][t] = 0.f;

    const int KT = kcount / BK;

    auto load_tile = [&](int kt, int st) {
        uint32_t base = sbase + st * STAGE_U32 * 4;
        #pragma unroll
        for (int t = 0; t < 4; t++) {
            int chunk = tid + t * 256;             // 0..1023
            int r = chunk >> 3, c4 = (chunk & 7) * 4;
            size_t aoff = (size_t)(row0 + r) * Kfull + kbase + kt * BK + (chunk & 7) * 8;
            cpa16(base + (uint32_t)(A_OFF + r * RSTR + c4) * 4, Ah + aoff);
            size_t boff = (size_t)(col0 + r) * Kfull + kbase + kt * BK + (chunk & 7) * 8;
            cpa16(base + (uint32_t)(BH_OFF + r * RSTR + c4) * 4, Bh + boff);
            cpa16(base + (uint32_t)(BL_OFF + r * RSTR + c4) * 4, Bl + boff);
        }
        cp_commit();
    };

    load_tile(0, 0);
    for (int kt = 0; kt < KT; kt++) {
        if (kt + 1 < KT) { load_tile(kt + 1, (kt + 1) & 1); cp_wait1(); }
        else             { cp_wait0(); }
        __syncthreads();

        const uint32_t Sb = sbase + (uint32_t)(kt & 1) * STAGE_U32 * 4;

        #pragma unroll
        for (int ks = 0; ks < 4; ks++) {
            uint32_t af[4][4], bh[4][2], bl[4][2];
            // A fragments: lanes 0-15 -> rows (base..base+15) at k+0; lanes 16-31 same rows at +4 u32
            #pragma unroll
            for (int mi = 0; mi < 4; mi++) {
                uint32_t ao = Sb + (uint32_t)(A_OFF +
                    (wm * 64 + mi * 16 + lane15) * RSTR + ks * 8 + laneHi * 4) * 4;
                ldsm_x4(af[mi][0], af[mi][1], af[mi][2], af[mi][3], ao);
            }
            // B fragments: two 16-row n-blocks per warp, hi and lo
            #pragma unroll
            for (int p = 0; p < 2; p++) {
                uint32_t bo = Sb + (uint32_t)(BH_OFF +
                    (wn * 32 + p * 16 + lane15) * RSTR + ks * 8 + laneHi * 4) * 4;
                ldsm_x4(bh[2*p][0], bh[2*p+1][0], bh[2*p][1], bh[2*p+1][1], bo);
                uint32_t blo = bo + (uint32_t)(BL_OFF - BH_OFF) * 4;
                ldsm_x4(bl[2*p][0], bl[2*p+1][0], bl[2*p][1], bl[2*p+1][1], blo);
            }
            #pragma unroll
            for (int mi = 0; mi < 4; mi++)
                #pragma unroll
                for (int ni = 0; ni < 4; ni++) {
                    mma_fp16(acc[mi][ni], af[mi], bl[ni]);
                    mma_fp16(acc[mi][ni], af[mi], bh[ni]);
                }
        }
        __syncthreads();
    }

    // epilogue (C layout: t0=(g,2q) t1=(g,2q+1) t2=(g+8,2q) t3=(g+8,2q+1))
    #pragma unroll
    for (int mi = 0; mi < 4; mi++) {
        #pragma unroll
        for (int ni = 0; ni < 4; ni++) {
            int r0 = row0 + wm * 64 + mi * 16 + g;
            int c0 = col0 + wn * 32 + ni * 8 + 2 * q;
            float bb0 = PART ? 0.f : bias[c0];
            float bb1 = PART ? 0.f : bias[c0 + 1];
            #pragma unroll
            for (int h = 0; h < 2; h++) {
                int r = r0 + h * 8;
                float v0 = acc[mi][ni][2 * h]     + bb0;
                float v1 = acc[mi][ni][2 * h + 1] + bb1;
                if (GELU) {
                    v0 = 0.5f * v0 * (1.0f + erff(v0 * 0.70710678118654752f));
                    v1 = 0.5f * v1 * (1.0f + erff(v1 * 0.70710678118654752f));
                }
                if (RES) {
                    v0 += res[(size_t)r * N + c0];
                    v1 += res[(size_t)r * N + c0 + 1];
                }
                if (OHALF) {
                    Ch[(size_t)r * N + c0]     = __float2half_rn(v0);
                    Ch[(size_t)r * N + c0 + 1] = __float2half_rn(v1);
                } else {
                    C[(size_t)r * N + c0]     = v0;
                    C[(size_t)r * N + c0 + 1] = v1;
                }
            }
        }
    }
}

template<bool GELU, bool RES, bool OHALF>
__global__ void __launch_bounds__(256, 2)
gemm_tc(const __half* __restrict__ Ah,
        const __half* __restrict__ Bh, const __half* __restrict__ Bl,
        const float* __restrict__ bias, const float* __restrict__ res,
        float* __restrict__ C, __half* __restrict__ Ch, int N, int K) {
    extern __shared__ uint32_t smem[];
    gemm_body<GELU, RES, OHALF, false>(Ah, Bh, Bl, bias, res, C, Ch,
                                       N, K, 0, K, blockIdx.y * BM, blockIdx.x * BN, smem);
}

// split-K partial GEMM: blockIdx.z = split index, writes raw fp32 partials
__global__ void __launch_bounds__(256, 2)
gemm_part_k(const __half* __restrict__ Ah,
            const __half* __restrict__ Bh, const __half* __restrict__ Bl,
            float* __restrict__ parts, int N, int Kfull, int ksplit) {
    extern __shared__ uint32_t smem[];
    float* Cp = parts + (size_t)blockIdx.z * SQ * N;
    gemm_body<false, false, false, true>(Ah, Bh, Bl, nullptr, nullptr, Cp, nullptr,
                                         N, Kfull, blockIdx.z * ksplit, ksplit,
                                         blockIdx.y * BM, blockIdx.x * BN, smem);
}

// fused QKV: grid.x = 3 * (EM/BN); Q -> fp16, K/V -> fp32
__global__ void __launch_bounds__(256, 2)
qkv_tc(const __half* __restrict__ Bq_hi, const __half* __restrict__ Bq_lo,
       const __half* __restrict__ Bk_hi, const __half* __restrict__ Bk_lo,
       const __half* __restrict__ Bv_hi, const __half* __restrict__ Bv_lo,
       const float* __restrict__ bq, const float* __restrict__ bk, const float* __restrict__ bv) {
    extern __shared__ uint32_t smem[];
    const int nb = EM / BN;   // 6
    int m = blockIdx.x / nb, cb = blockIdx.x % nb;
    if (m == 0) {
        gemm_body<false, false, true, false>(g_h, Bq_hi, Bq_lo, bq, nullptr, nullptr, g_qh,
                                             EM, EM, 0, EM, blockIdx.y * BM, cb * BN, smem);
    } else {
        const __half* Bh = (m == 1) ? Bk_hi : Bv_hi;
        const __half* Bl = (m == 1) ? Bk_lo : Bv_lo;
        const float*  b  = (m == 1) ? bk : bv;
        float*        C  = (m == 1) ? g_k : g_v;
        gemm_body<false, false, false, false>(g_h, Bh, Bl, b, nullptr, C, nullptr,
                                              EM, EM, 0, EM, blockIdx.y * BM, cb * BN, smem);
    }
}

// ---------------- attention part 1: partial M = K_h^T V_h over an S-chunk ----------------
__global__ void __launch_bounds__(256) attn_m_k() {
    const int h = blockIdx.x, chunk = blockIdx.y;
    __shared__ float Ks[32][65];
    __shared__ float Vs[32][65];
    const int tid = threadIdx.x;
    const int tx = tid & 15, ty = tid >> 4;
    float acc[4][4] = {};
    const int sbase = chunk * (SQ / NCHUNK);
    for (int s0 = 0; s0 < SQ / NCHUNK; s0 += 32) {
        #pragma unroll
        for (int i = 0; i < 8; i++) {
            int idx = tid + i * 256;
            int r = idx >> 6, c = idx & 63;
            int gidx = (sbase + s0 + r) * EM + h * 64 + c;
            Ks[r][c] = g_k[gidx];
            Vs[r][c] = g_v[gidx];
        }
        __syncthreads();
        #pragma unroll
        for (int ss = 0; ss < 32; ss++) {
            float a[4], bb[4];
            #pragma unroll
            for (int i = 0; i < 4; i++) a[i]  = Ks[ss][ty + i * 16];
            #pragma unroll
            for (int j = 0; j < 4; j++) bb[j] = Vs[ss][tx + j * 16];
            #pragma unroll
            for (int i = 0; i < 4; i++)
                #pragma unroll
                for (int j = 0; j < 4; j++)
                    acc[i][j] += a[i] * bb[j];
        }
        __syncthreads();
    }
    #pragma unroll
    for (int i = 0; i < 4; i++)
        #pragma unroll
        for (int j = 0; j < 4; j++)
            g_Mp[((h * NCHUNK + chunk) * 64 + ty + i * 16) * 64 + tx + j * 16] = acc[i][j];
}

// ---------------- N = scale * M * Wo  (per head, transposed + split fp16) ----------------
__global__ void __launch_bounds__(256) nmat_k(const float* __restrict__ Wo) {
    const int h = blockIdx.x, ob = blockIdx.y;
    __shared__ float Ms[64][65];
    __shared__ float Ws[64][65];
    const int tid = threadIdx.x;
    #pragma unroll
    for (int i = 0; i < 16; i++) {
        int idx = tid + i * 256;
        int d1 = idx >> 6, d2 = idx & 63;
        float s = 0.f;
        #pragma unroll
        for (int c = 0; c < NCHUNK; c++)
            s += g_Mp[((h * NCHUNK + c) * 64 + d1) * 64 + d2];
        Ms[d1][d2] = s * 0.125f;   // DH^-0.5
        int e = idx >> 6, o = idx & 63;
        Ws[e][o] = Wo[(size_t)(h * 64 + e) * EM + ob * 64 + o];
    }
    __syncthreads();
    const int o = tid & 63, dbase = (tid >> 6) * 16;
    #pragma unroll
    for (int dd = 0; dd < 16; dd++) {
        int d = dbase + dd;
        float s = 0.f;
        #pragma unroll
        for (int e = 0; e < 64; e++)
            s += Ms[d][e] * Ws[e][o];
        __half hi, lo;
        split_fp16(s, hi, lo);
        size_t off = (size_t)(ob * 64 + o) * EM + h * 64 + d;
        g_nh[off] = hi;
        g_nl[off] = lo;
    }
}

// ---------------- host ----------------
extern "C" void kernel_launch(void* const* d_in, const int* in_sizes, int n_in,
                              void* d_out, int out_size) {
    const float* emb   = (const float*)d_in[0];
    const float* wpe   = (const float*)d_in[1];
    const float* ln1_g = (const float*)d_in[2];
    const float* ln1_b = (const float*)d_in[3];
    const float* Wq    = (const float*)d_in[4];
    const float* bq    = (const float*)d_in[5];
    const float* Wk    = (const float*)d_in[6];
    const float* bk    = (const float*)d_in[7];
    const float* Wv    = (const float*)d_in[8];
    const float* bv    = (const float*)d_in[9];
    const float* Wo    = (const float*)d_in[10];
    const float* bo    = (const float*)d_in[11];
    const float* ln2_g = (const float*)d_in[12];
    const float* ln2_b = (const float*)d_in[13];
    const float* W1    = (const float*)d_in[14];
    const float* b1    = (const float*)d_in[15];
    const float* W2    = (const float*)d_in[16];
    const float* b2    = (const float*)d_in[17];
    const float* lnf_g = (const float*)d_in[18];
    const float* lnf_b = (const float*)d_in[19];
    float* out = (float*)d_out;

    float *px, *ppart;
    __half *pwh, *pwl, *pnh, *pnl, *pqh, *phh, *pff;
    cudaGetSymbolAddress((void**)&px,    g_x);
    cudaGetSymbolAddress((void**)&ppart, g_part);
    cudaGetSymbolAddress((void**)&pwh,   gwt_hi);
    cudaGetSymbolAddress((void**)&pwl,   gwt_lo);
    cudaGetSymbolAddress((void**)&pnh,   g_nh);
    cudaGetSymbolAddress((void**)&pnl,   g_nl);
    cudaGetSymbolAddress((void**)&pqh,   g_qh);
    cudaGetSymbolAddress((void**)&phh,   g_h);
    cudaGetSymbolAddress((void**)&pff,   g_ff);

    cudaFuncSetAttribute(gemm_tc<true, false, true>,
                         cudaFuncAttributeMaxDynamicSharedMemorySize, SMEM_BYTES);
    cudaFuncSetAttribute(gemm_part_k,
                         cudaFuncAttributeMaxDynamicSharedMemorySize, SMEM_BYTES);
    cudaFuncSetAttribute(qkv_tc,
                         cudaFuncAttributeMaxDynamicSharedMemorySize, SMEM_BYTES);

    // weight transpose + hi/lo split (Wo excluded — fused via N)
    {
        dim3 blk(32, 8);
        wconv_k<true><<<dim3(EM/32, EM/32, 3*NL), blk>>>(
            Wq, Wk, Wv, pwh + OFF_WQ, pwl + OFF_WQ, EM, EM, WMAT);
        wconv_k<false><<<dim3(FFD/32, EM/32,  NL), blk>>>(
            W1, nullptr, nullptr, pwh + OFF_W1, pwl + OFF_W1, EM,  FFD, W1MAT);
        wconv_k<false><<<dim3(EM/32,  FFD/32, NL), blk>>>(
            W2, nullptr, nullptr, pwh + OFF_W2, pwl + OFF_W2, FFD, EM,  W1MAT);
    }

    const dim3 gQKV(3 * (EM / BN), SQ / BM);     // (18, 16)
    const dim3 gS(EM / BN, SQ / BM, 3);          // split-K grids (6, 16, 3)
    const dim3 gF(FFD / BN, SQ / BM);            // (24, 16)

    // x = emb + wpe fused with LN1 (layer 0)
    addln_k<<<SQ, 256>>>(emb, wpe, px, phh, ln1_g, ln1_b);

    for (int l = 0; l < NL; l++) {
        const __half* wq_h = pwh + OFF_WQ + (size_t)l * WMAT;
        const __half* wq_l = pwl + OFF_WQ + (size_t)l * WMAT;
        const __half* wk_h = pwh + OFF_WK + (size_t)l * WMAT;
        const __half* wk_l = pwl + OFF_WK + (size_t)l * WMAT;
        const __half* wv_h = pwh + OFF_WV + (size_t)l * WMAT;
        const __half* wv_l = pwl + OFF_WV + (size_t)l * WMAT;
        const __half* w1_h = pwh + OFF_W1 + (size_t)l * W1MAT;
        const __half* w1_l = pwl + OFF_W1 + (size_t)l * W1MAT;
        const __half* w2_h = pwh + OFF_W2 + (size_t)l * W1MAT;
        const __half* w2_l = pwl + OFF_W2 + (size_t)l * W1MAT;

        qkv_tc<<<gQKV, 256, SMEM_BYTES>>>(wq_h, wq_l, wk_h, wk_l, wv_h, wv_l,
                                          bq + l * EM, bk + l * EM, bv + l * EM);
        attn_m_k<<<dim3(NH, NCHUNK), 256>>>();
        nmat_k<<<dim3(NH, EM / 64), 256>>>(Wo + (size_t)l * EM * EM);

        // O-projection: split-K=3 (K=768 -> 256 each), combine + LN2 fused
        gemm_part_k<<<gS, 256, SMEM_BYTES>>>(pqh, pnh, pnl, ppart, EM, EM, EM / 3);
        combine_ln_k<true><<<SQ, 256>>>(ppart, bo + l * EM, px, nullptr, phh,
                                        ln2_g + l * EM, ln2_b + l * EM);

        gemm_tc<true, false, true><<<gF, 256, SMEM_BYTES>>>(
            phh, w1_h, w1_l, b1 + l * FFD, nullptr, nullptr, pff, FFD, EM);

        // W2: split-K=3 (K=3072 -> 1024 each), combine + next LN fused
        gemm_part_k<<<gS, 256, SMEM_BYTES>>>(pff, w2_h, w2_l, ppart, EM, FFD, FFD / 3);
        if (l + 1 < NL) {
            combine_ln_k<true><<<SQ, 256>>>(ppart, b2 + l * EM, px, nullptr, phh,
                                            ln1_g + (l + 1) * EM, ln1_b + (l + 1) * EM);
        } else {
            combine_ln_k<false><<<SQ, 256>>>(ppart, b2 + l * EM, px, out, nullptr,
                                             lnf_g, lnf_b);
        }
    }
}

// round 13
// speedup vs baseline: 1.0612x; 1.0612x over previous
#include <cuda_runtime.h>
#include <cuda_fp16.h>
#include <math.h>
#include <stdint.h>

#define SQ   2048
#define EM   768
#define NH   12
#define DH   64
#define FFD  3072
#define NL   4
#define EPSF 1e-5f
#define NCHUNK 32

// GEMM tiling: BM=BN=128, BK=64 halves, 256 threads, warp tile 64x32 (R11 config)
#define BM 128
#define BN 128
#define BK 64
#define RSTR 36            // smem row stride in u32 (32 used + 4 pad)
#define A_OFF 0
#define BH_OFF 4608
#define BL_OFF 9216
#define STAGE_U32 13824
#define SMEM_BYTES (2*STAGE_U32*4)   // 110592

// weight pool offsets (elements) — Wq,Wk,Wv,W1,W2 (Wo handled via N fusion)
#define WMAT   589824            // 768*768
#define W1MAT  2359296           // 768*3072
#define OFF_WQ 0
#define OFF_WK (4*WMAT)
#define OFF_WV (8*WMAT)
#define OFF_W1 (12*WMAT)
#define OFF_W2 (12*WMAT + 4*W1MAT)
#define WTOTAL (12*WMAT + 8*W1MAT)

// ---------------- scratch (no allocations allowed) ----------------
__device__ float g_x[SQ*EM];                 // residual stream (fp32)
__device__ float g_k[SQ*EM];                 // K (fp32)
__device__ float g_v[SQ*EM];                 // V (fp32)
__device__ float g_Mp[NH*NCHUNK*DH*DH];      // partial K^T V
__device__ float g_part[3*SQ*EM];            // split-K partials
__device__ __half g_qh[SQ*EM];               // Q (fp16)
__device__ __half g_h[SQ*EM];                // LN output (fp16)
__device__ __half g_ff[SQ*FFD];              // MLP hidden (fp16)
__device__ __half gwt_hi[WTOTAL];            // transposed weights hi
__device__ __half gwt_lo[WTOTAL];            // transposed weights lo
__device__ __half g_nh[EM*EM];               // N = scale*M*Wo, transposed, hi
__device__ __half g_nl[EM*EM];               // N lo

// ---------------- helpers ----------------
__device__ __forceinline__ void mma_fp16(float c[4], const uint32_t a[4], const uint32_t b[2]) {
    asm volatile(
        "mma.sync.aligned.m16n8k16.row.col.f32.f16.f16.f32 "
        "{%0,%1,%2,%3},{%4,%5,%6,%7},{%8,%9},{%0,%1,%2,%3};\n"
        : "+f"(c[0]), "+f"(c[1]), "+f"(c[2]), "+f"(c[3])
        : "r"(a[0]), "r"(a[1]), "r"(a[2]), "r"(a[3]), "r"(b[0]), "r"(b[1]));
}
__device__ __forceinline__ void cpa16(uint32_t dst, const void* src) {
    asm volatile("cp.async.cg.shared.global [%0], [%1], 16;\n" :: "r"(dst), "l"(src) : "memory");
}
__device__ __forceinline__ void cp_commit() { asm volatile("cp.async.commit_group;\n" ::: "memory"); }
__device__ __forceinline__ void cp_wait1()  { asm volatile("cp.async.wait_group 1;\n" ::: "memory"); }
__device__ __forceinline__ void cp_wait0()  { asm volatile("cp.async.wait_group 0;\n" ::: "memory"); }

__device__ __forceinline__ void split_fp16(float v, __half& hi, __half& lo) {
    hi = __float2half_rn(v);
    lo = __float2half_rn(v - __half2float(hi));
}

// ---------------- weight transpose + split: src[L][K][N] -> dst[L][N][K] (hi,lo fp16) ----------------
template<bool QKV>
__global__ void wconv_k(const float* __restrict__ s0, const float* __restrict__ s1,
                        const float* __restrict__ s2,
                        __half* __restrict__ dhi, __half* __restrict__ dlo,
                        int K, int N, int poolStride) {
    __shared__ float t[32][33];
    int m = 0, l = blockIdx.z;
    if (QKV) { m = blockIdx.z / NL; l = blockIdx.z % NL; }
    const float* src = (m == 0) ? s0 : (m == 1) ? s1 : s2;
    const size_t lofs = (size_t)l * K * N;
    const size_t dofs = (size_t)m * 4 * WMAT + (size_t)l * poolStride;
    const int n0 = blockIdx.x * 32, k0 = blockIdx.y * 32;
    const int tx = threadIdx.x, ty = threadIdx.y;
    #pragma unroll
    for (int i = 0; i < 4; i++)
        t[ty + 8*i][tx] = src[lofs + (size_t)(k0 + ty + 8*i) * N + n0 + tx];
    __syncthreads();
    const int u = tx & 15, nx = tx >> 4;
    #pragma unroll
    for (int i = 0; i < 2; i++) {
        int n = ty + 8*i + 16*nx;
        float v0 = t[2*u][n], v1 = t[2*u + 1][n];
        __half h0, l0, h1, l1;
        split_fp16(v0, h0, l0);
        split_fp16(v1, h1, l1);
        size_t o = dofs + (size_t)(n0 + n) * K + k0 + 2*u;
        *reinterpret_cast<__half2*>(dhi + o) = __halves2half2(h0, h1);
        *reinterpret_cast<__half2*>(dlo + o) = __halves2half2(l0, l1);
    }
}

// ---------------- initial: x = emb + wpe, then LN -> fp16 ----------------
__global__ void __launch_bounds__(256)
addln_k(const float* __restrict__ emb, const float* __restrict__ wpe,
        float* __restrict__ px, __half* __restrict__ oh,
        const float* __restrict__ g, const float* __restrict__ b) {
    const int row = blockIdx.x;
    float loc[3];
    float s = 0.f, s2 = 0.f;
    #pragma unroll
    for (int t = 0; t < 3; t++) {
        int j = threadIdx.x + t * 256;
        size_t o = (size_t)row * EM + j;
        float v = emb[o] + wpe[o];
        px[o] = v;
        loc[t] = v;
        s += v; s2 += v * v;
    }
    __shared__ float rs[32], rs2[32];
    #pragma unroll
    for (int o = 16; o; o >>= 1) {
        s  += __shfl_down_sync(0xffffffffu, s,  o);
        s2 += __shfl_down_sync(0xffffffffu, s2, o);
    }
    int w = threadIdx.x >> 5, l = threadIdx.x & 31;
    if (l == 0) { rs[w] = s; rs2[w] = s2; }
    __syncthreads();
    if (w == 0) {
        s  = (l < 8) ? rs[l]  : 0.f;
        s2 = (l < 8) ? rs2[l] : 0.f;
        #pragma unroll
        for (int o = 4; o; o >>= 1) {
            s  += __shfl_down_sync(0xffffffffu, s,  o);
            s2 += __shfl_down_sync(0xffffffffu, s2, o);
        }
        if (l == 0) { rs[0] = s; rs2[0] = s2; }
    }
    __syncthreads();
    float mu  = rs[0] * (1.0f / EM);
    float var = rs2[0] * (1.0f / EM) - mu * mu;
    float inv = rsqrtf(var + EPSF);
    #pragma unroll
    for (int t = 0; t < 3; t++) {
        int j = threadIdx.x + t * 256;
        oh[(size_t)row * EM + j] = __float2half_rn((loc[t] - mu) * inv * g[j] + b[j]);
    }
}

// ---------------- combine 3 split-K partials + bias + residual, then LayerNorm ----------------
template<bool HALF>
__global__ void __launch_bounds__(256)
combine_ln_k(const float* __restrict__ parts, const float* __restrict__ bias,
             float* __restrict__ px, float* __restrict__ outf, __half* __restrict__ oh,
             const float* __restrict__ g, const float* __restrict__ b) {
    const int row = blockIdx.x;
    float loc[3];
    float s = 0.f, s2 = 0.f;
    #pragma unroll
    for (int t = 0; t < 3; t++) {
        int j = threadIdx.x + t * 256;
        size_t o = (size_t)row * EM + j;
        float v = px[o] + bias[j] + parts[o] + parts[o + (size_t)SQ*EM] + parts[o + 2*(size_t)SQ*EM];
        px[o] = v;
        loc[t] = v;
        s += v; s2 += v * v;
    }
    __shared__ float rs[32], rs2[32];
    #pragma unroll
    for (int o = 16; o; o >>= 1) {
        s  += __shfl_down_sync(0xffffffffu, s,  o);
        s2 += __shfl_down_sync(0xffffffffu, s2, o);
    }
    int w = threadIdx.x >> 5, l = threadIdx.x & 31;
    if (l == 0) { rs[w] = s; rs2[w] = s2; }
    __syncthreads();
    if (w == 0) {
        s  = (l < 8) ? rs[l]  : 0.f;
        s2 = (l < 8) ? rs2[l] : 0.f;
        #pragma unroll
        for (int o = 4; o; o >>= 1) {
            s  += __shfl_down_sync(0xffffffffu, s,  o);
            s2 += __shfl_down_sync(0xffffffffu, s2, o);
        }
        if (l == 0) { rs[0] = s; rs2[0] = s2; }
    }
    __syncthreads();
    float mu  = rs[0] * (1.0f / EM);
    float var = rs2[0] * (1.0f / EM) - mu * mu;
    float inv = rsqrtf(var + EPSF);
    #pragma unroll
    for (int t = 0; t < 3; t++) {
        int j = threadIdx.x + t * 256;
        float v = (loc[t] - mu) * inv * g[j] + b[j];
        if (HALF) oh[(size_t)row * EM + j] = __float2half_rn(v);
        else      outf[(size_t)row * EM + j] = v;
    }
}

// ---------------- 2-term fp16 tensor-core GEMM body (BK=64, scalar LDS fragments) ----------------
// A (fp16, [M,Kfull] row-major), B (hi/lo fp16, [N,Kfull] k-major)
template<bool GELU, bool RES, bool OHALF, bool PART>
__device__ __forceinline__ void gemm_body(
    const __half* __restrict__ Ah,
    const __half* __restrict__ Bh, const __half* __restrict__ Bl,
    const float* __restrict__ bias, const float* __restrict__ res,
    float* __restrict__ C, __half* __restrict__ Ch,
    int N, int Kfull, int kbase, int kcount, int row0, int col0, uint32_t* smem)
{
    const int tid  = threadIdx.x;
    const int lane = tid & 31, warp = tid >> 5;
    const int wm = warp >> 2, wn = warp & 3;   // 2 x 4 warp grid
    const int g = lane >> 2, q = lane & 3;

    uint32_t sbase = (uint32_t)__cvta_generic_to_shared(smem);

    float acc[4][4][4];
    #pragma unroll
    for (int i = 0; i < 4; i++)
        #pragma unroll
        for (int j = 0; j < 4; j++)
            #pragma unroll
            for (int t = 0; t < 4; t++) acc[i][j][t] = 0.f;

    const int KT = kcount / BK;

    auto load_tile = [&](int kt, int st) {
        uint32_t base = sbase + st * STAGE_U32 * 4;
        #pragma unroll
        for (int t = 0; t < 4; t++) {
            int chunk = tid + t * 256;             // 0..1023
            int r = chunk >> 3, c4 = (chunk & 7) * 4;
            size_t aoff = (size_t)(row0 + r) * Kfull + kbase + kt * BK + (chunk & 7) * 8;
            cpa16(base + (uint32_t)(A_OFF + r * RSTR + c4) * 4, Ah + aoff);
            size_t boff = (size_t)(col0 + r) * Kfull + kbase + kt * BK + (chunk & 7) * 8;
            cpa16(base + (uint32_t)(BH_OFF + r * RSTR + c4) * 4, Bh + boff);
            cpa16(base + (uint32_t)(BL_OFF + r * RSTR + c4) * 4, Bl + boff);
        }
        cp_commit();
    };

    load_tile(0, 0);
    for (int kt = 0; kt < KT; kt++) {
        if (kt + 1 < KT) { load_tile(kt + 1, (kt + 1) & 1); cp_wait1(); }
        else             { cp_wait0(); }
        __syncthreads();

        const uint32_t* S = smem + (kt & 1) * STAGE_U32;

        #pragma unroll
        for (int ks = 0; ks < 4; ks++) {
            const int kq = ks * 8 + q;
            uint32_t af[4][4], bh[4][2], bl[4][2];
            #pragma unroll
            for (int mi = 0; mi < 4; mi++) {
                int rb = (wm * 64 + mi * 16 + g) * RSTR + kq;
                af[mi][0] = S[A_OFF + rb];       af[mi][1] = S[A_OFF + rb + 8*RSTR];
                af[mi][2] = S[A_OFF + rb + 4];   af[mi][3] = S[A_OFF + rb + 8*RSTR + 4];
            }
            #pragma unroll
            for (int ni = 0; ni < 4; ni++) {
                int nb = (wn * 32 + ni * 8 + g) * RSTR + kq;
                bh[ni][0] = S[BH_OFF + nb];  bh[ni][1] = S[BH_OFF + nb + 4];
                bl[ni][0] = S[BL_OFF + nb];  bl[ni][1] = S[BL_OFF + nb + 4];
            }
            #pragma unroll
            for (int mi = 0; mi < 4; mi++)
                #pragma unroll
                for (int ni = 0; ni < 4; ni++) {
                    mma_fp16(acc[mi][ni], af[mi], bl[ni]);
                    mma_fp16(acc[mi][ni], af[mi], bh[ni]);
                }
        }
        __syncthreads();
    }

    // epilogue (C layout: t0=(g,2q) t1=(g,2q+1) t2=(g+8,2q) t3=(g+8,2q+1))
    #pragma unroll
    for (int mi = 0; mi < 4; mi++) {
        #pragma unroll
        for (int ni = 0; ni < 4; ni++) {
            int r0 = row0 + wm * 64 + mi * 16 + g;
            int c0 = col0 + wn * 32 + ni * 8 + 2 * q;
            float bb0 = PART ? 0.f : bias[c0];
            float bb1 = PART ? 0.f : bias[c0 + 1];
            #pragma unroll
            for (int h = 0; h < 2; h++) {
                int r = r0 + h * 8;
                float v0 = acc[mi][ni][2 * h]     + bb0;
                float v1 = acc[mi][ni][2 * h + 1] + bb1;
                if (GELU) {
                    v0 = 0.5f * v0 * (1.0f + erff(v0 * 0.70710678118654752f));
                    v1 = 0.5f * v1 * (1.0f + erff(v1 * 0.70710678118654752f));
                }
                if (RES) {
                    v0 += res[(size_t)r * N + c0];
                    v1 += res[(size_t)r * N + c0 + 1];
                }
                if (OHALF) {
                    Ch[(size_t)r * N + c0]     = __float2half_rn(v0);
                    Ch[(size_t)r * N + c0 + 1] = __float2half_rn(v1);
                } else {
                    C[(size_t)r * N + c0]     = v0;
                    C[(size_t)r * N + c0 + 1] = v1;
                }
            }
        }
    }
}

template<bool GELU, bool RES, bool OHALF>
__global__ void __launch_bounds__(256, 2)
gemm_tc(const __half* __restrict__ Ah,
        const __half* __restrict__ Bh, const __half* __restrict__ Bl,
        const float* __restrict__ bias, const float* __restrict__ res,
        float* __restrict__ C, __half* __restrict__ Ch, int N, int K) {
    extern __shared__ uint32_t smem[];
    gemm_body<GELU, RES, OHALF, false>(Ah, Bh, Bl, bias, res, C, Ch,
                                       N, K, 0, K, blockIdx.y * BM, blockIdx.x * BN, smem);
}

// split-K partial GEMM: blockIdx.z = split index, writes raw fp32 partials
__global__ void __launch_bounds__(256, 2)
gemm_part_k(const __half* __restrict__ Ah,
            const __half* __restrict__ Bh, const __half* __restrict__ Bl,
            float* __restrict__ parts, int N, int Kfull, int ksplit) {
    extern __shared__ uint32_t smem[];
    float* Cp = parts + (size_t)blockIdx.z * SQ * N;
    gemm_body<false, false, false, true>(Ah, Bh, Bl, nullptr, nullptr, Cp, nullptr,
                                         N, Kfull, blockIdx.z * ksplit, ksplit,
                                         blockIdx.y * BM, blockIdx.x * BN, smem);
}

// K+V projection: grid.x = 2 * (EM/BN); outputs fp32 K and V
__global__ void __launch_bounds__(256, 2)
kv_tc(const __half* __restrict__ Bk_hi, const __half* __restrict__ Bk_lo,
      const __half* __restrict__ Bv_hi, const __half* __restrict__ Bv_lo,
      const float* __restrict__ bk, const float* __restrict__ bv) {
    extern __shared__ uint32_t smem[];
    const int nb = EM / BN;   // 6
    int m = blockIdx.x / nb, cb = blockIdx.x % nb;
    const __half* Bh = (m == 0) ? Bk_hi : Bv_hi;
    const __half* Bl = (m == 0) ? Bk_lo : Bv_lo;
    const float*  b  = (m == 0) ? bk : bv;
    float*        C  = (m == 0) ? g_k : g_v;
    gemm_body<false, false, false, false>(g_h, Bh, Bl, b, nullptr, C, nullptr,
                                          EM, EM, 0, EM, blockIdx.y * BM, cb * BN, smem);
}

// Q projection (side stream): outputs fp16 Q
__global__ void __launch_bounds__(256, 2)
q_tc(const __half* __restrict__ Bq_hi, const __half* __restrict__ Bq_lo,
     const float* __restrict__ bq) {
    extern __shared__ uint32_t smem[];
    gemm_body<false, false, true, false>(g_h, Bq_hi, Bq_lo, bq, nullptr, nullptr, g_qh,
                                         EM, EM, 0, EM, blockIdx.y * BM, blockIdx.x * BN, smem);
}

// ---------------- attention part 1: partial M = K_h^T V_h over an S-chunk ----------------
__global__ void __launch_bounds__(256) attn_m_k() {
    const int h = blockIdx.x, chunk = blockIdx.y;
    __shared__ float Ks[32][65];
    __shared__ float Vs[32][65];
    const int tid = threadIdx.x;
    const int tx = tid & 15, ty = tid >> 4;
    float acc[4][4] = {};
    const int sbase = chunk * (SQ / NCHUNK);
    for (int s0 = 0; s0 < SQ / NCHUNK; s0 += 32) {
        #pragma unroll
        for (int i = 0; i < 8; i++) {
            int idx = tid + i * 256;
            int r = idx >> 6, c = idx & 63;
            int gidx = (sbase + s0 + r) * EM + h * 64 + c;
            Ks[r][c] = g_k[gidx];
            Vs[r][c] = g_v[gidx];
        }
        __syncthreads();
        #pragma unroll
        for (int ss = 0; ss < 32; ss++) {
            float a[4], bb[4];
            #pragma unroll
            for (int i = 0; i < 4; i++) a[i]  = Ks[ss][ty + i * 16];
            #pragma unroll
            for (int j = 0; j < 4; j++) bb[j] = Vs[ss][tx + j * 16];
            #pragma unroll
            for (int i = 0; i < 4; i++)
                #pragma unroll
                for (int j = 0; j < 4; j++)
                    acc[i][j] += a[i] * bb[j];
        }
        __syncthreads();
    }
    #pragma unroll
    for (int i = 0; i < 4; i++)
        #pragma unroll
        for (int j = 0; j < 4; j++)
            g_Mp[((h * NCHUNK + chunk) * 64 + ty + i * 16) * 64 + tx + j * 16] = acc[i][j];
}

// ---------------- N = scale * M * Wo  (per head, transposed + split fp16) ----------------
__global__ void __launch_bounds__(256) nmat_k(const float* __restrict__ Wo) {
    const int h = blockIdx.x, ob = blockIdx.y;
    __shared__ float Ms[64][65];
    __shared__ float Ws[64][65];
    const int tid = threadIdx.x;
    #pragma unroll
    for (int i = 0; i < 16; i++) {
        int idx = tid + i * 256;
        int d1 = idx >> 6, d2 = idx & 63;
        float s = 0.f;
        #pragma unroll
        for (int c = 0; c < NCHUNK; c++)
            s += g_Mp[((h * NCHUNK + c) * 64 + d1) * 64 + d2];
        Ms[d1][d2] = s * 0.125f;   // DH^-0.5
        int e = idx >> 6, o = idx & 63;
        Ws[e][o] = Wo[(size_t)(h * 64 + e) * EM + ob * 64 + o];
    }
    __syncthreads();
    const int o = tid & 63, dbase = (tid >> 6) * 16;
    #pragma unroll
    for (int dd = 0; dd < 16; dd++) {
        int d = dbase + dd;
        float s = 0.f;
        #pragma unroll
        for (int e = 0; e < 64; e++)
            s += Ms[d][e] * Ws[e][o];
        __half hi, lo;
        split_fp16(s, hi, lo);
        size_t off = (size_t)(ob * 64 + o) * EM + h * 64 + d;
        g_nh[off] = hi;
        g_nl[off] = lo;
    }
}

// ---------------- host ----------------
extern "C" void kernel_launch(void* const* d_in, const int* in_sizes, int n_in,
                              void* d_out, int out_size) {
    const float* emb   = (const float*)d_in[0];
    const float* wpe   = (const float*)d_in[1];
    const float* ln1_g = (const float*)d_in[2];
    const float* ln1_b = (const float*)d_in[3];
    const float* Wq    = (const float*)d_in[4];
    const float* bq    = (const float*)d_in[5];
    const float* Wk    = (const float*)d_in[6];
    const float* bk    = (const float*)d_in[7];
    const float* Wv    = (const float*)d_in[8];
    const float* bv    = (const float*)d_in[9];
    const float* Wo    = (const float*)d_in[10];
    const float* bo    = (const float*)d_in[11];
    const float* ln2_g = (const float*)d_in[12];
    const float* ln2_b = (const float*)d_in[13];
    const float* W1    = (const float*)d_in[14];
    const float* b1    = (const float*)d_in[15];
    const float* W2    = (const float*)d_in[16];
    const float* b2    = (const float*)d_in[17];
    const float* lnf_g = (const float*)d_in[18];
    const float* lnf_b = (const float*)d_in[19];
    float* out = (float*)d_out;

    float *px, *ppart;
    __half *pwh, *pwl, *pnh, *pnl, *pqh, *phh, *pff;
    cudaGetSymbolAddress((void**)&px,    g_x);
    cudaGetSymbolAddress((void**)&ppart, g_part);
    cudaGetSymbolAddress((void**)&pwh,   gwt_hi);
    cudaGetSymbolAddress((void**)&pwl,   gwt_lo);
    cudaGetSymbolAddress((void**)&pnh,   g_nh);
    cudaGetSymbolAddress((void**)&pnl,   g_nl);
    cudaGetSymbolAddress((void**)&pqh,   g_qh);
    cudaGetSymbolAddress((void**)&phh,   g_h);
    cudaGetSymbolAddress((void**)&pff,   g_ff);

    cudaFuncSetAttribute(gemm_tc<true, false, true>,
                         cudaFuncAttributeMaxDynamicSharedMemorySize, SMEM_BYTES);
    cudaFuncSetAttribute(gemm_part_k,
                         cudaFuncAttributeMaxDynamicSharedMemorySize, SMEM_BYTES);
    cudaFuncSetAttribute(kv_tc,
                         cudaFuncAttributeMaxDynamicSharedMemorySize, SMEM_BYTES);
    cudaFuncSetAttribute(q_tc,
                         cudaFuncAttributeMaxDynamicSharedMemorySize, SMEM_BYTES);

    // side stream + fork/join events (host objects; created once, no device memory)
    static cudaStream_t s2 = nullptr;
    static cudaEvent_t evF = nullptr, evQ = nullptr, evW = nullptr;
    if (!s2) {
        cudaStreamCreateWithFlags(&s2, cudaStreamNonBlocking);
        cudaEventCreateWithFlags(&evF, cudaEventDisableTiming);
        cudaEventCreateWithFlags(&evQ, cudaEventDisableTiming);
        cudaEventCreateWithFlags(&evW, cudaEventDisableTiming);
    }

    dim3 wblk(32, 8);

    // fork: W1/W2 weight conversion on side stream (overlaps QKV wconv + layer-0 attn)
    cudaEventRecord(evF, 0);
    cudaStreamWaitEvent(s2, evF, 0);
    wconv_k<false><<<dim3(FFD/32, EM/32,  NL), wblk, 0, s2>>>(
        W1, nullptr, nullptr, pwh + OFF_W1, pwl + OFF_W1, EM,  FFD, W1MAT);
    wconv_k<false><<<dim3(EM/32,  FFD/32, NL), wblk, 0, s2>>>(
        W2, nullptr, nullptr, pwh + OFF_W2, pwl + OFF_W2, FFD, EM,  W1MAT);
    cudaEventRecord(evW, s2);

    // main stream: QKV weight conversion + initial add+LN
    wconv_k<true><<<dim3(EM/32, EM/32, 3*NL), wblk>>>(
        Wq, Wk, Wv, pwh + OFF_WQ, pwl + OFF_WQ, EM, EM, WMAT);
    addln_k<<<SQ, 256>>>(emb, wpe, px, phh, ln1_g, ln1_b);

    const dim3 gKV(2 * (EM / BN), SQ / BM);      // (12, 16)
    const dim3 gQ(EM / BN, SQ / BM);             // (6, 16)
    const dim3 gS(EM / BN, SQ / BM, 3);          // split-K grids (6, 16, 3)
    const dim3 gF(FFD / BN, SQ / BM);            // (24, 16)

    for (int l = 0; l < NL; l++) {
        const __half* wq_h = pwh + OFF_WQ + (size_t)l * WMAT;
        const __half* wq_l = pwl + OFF_WQ + (size_t)l * WMAT;
        const __half* wk_h = pwh + OFF_WK + (size_t)l * WMAT;
        const __half* wk_l = pwl + OFF_WK + (size_t)l * WMAT;
        const __half* wv_h = pwh + OFF_WV + (size_t)l * WMAT;
        const __half* wv_l = pwl + OFF_WV + (size_t)l * WMAT;
        const __half* w1_h = pwh + OFF_W1 + (size_t)l * W1MAT;
        const __half* w1_l = pwl + OFF_W1 + (size_t)l * W1MAT;
        const __half* w2_h = pwh + OFF_W2 + (size_t)l * W1MAT;
        const __half* w2_l = pwl + OFF_W2 + (size_t)l * W1MAT;

        // fork: Q projection on side stream, concurrent with KV + attn_m + nmat
        cudaEventRecord(evF, 0);
        cudaStreamWaitEvent(s2, evF, 0);
        q_tc<<<gQ, 256, SMEM_BYTES, s2>>>(wq_h, wq_l, bq + l * EM);
        cudaEventRecord(evQ, s2);

        kv_tc<<<gKV, 256, SMEM_BYTES>>>(wk_h, wk_l, wv_h, wv_l, bk + l * EM, bv + l * EM);
        attn_m_k<<<dim3(NH, NCHUNK), 256>>>();
        nmat_k<<<dim3(NH, EM / 64), 256>>>(Wo + (size_t)l * EM * EM);

        // join: O-projection needs Q
        cudaStreamWaitEvent(0, evQ, 0);
        gemm_part_k<<<gS, 256, SMEM_BYTES>>>(pqh, pnh, pnl, ppart, EM, EM, EM / 3);
        combine_ln_k<true><<<SQ, 256>>>(ppart, bo + l * EM, px, nullptr, phh,
                                        ln2_g + l * EM, ln2_b + l * EM);

        // join: first W1 use must wait for side-stream weight conversion
        if (l == 0) cudaStreamWaitEvent(0, evW, 0);
        gemm_tc<true, false, true><<<gF, 256, SMEM_BYTES>>>(
            phh, w1_h, w1_l, b1 + l * FFD, nullptr, nullptr, pff, FFD, EM);

        // W2: split-K=3 (K=3072 -> 1024 each), combine + next LN fused
        gemm_part_k<<<gS, 256, SMEM_BYTES>>>(pff, w2_h, w2_l, ppart, EM, FFD, FFD / 3);
        if (l + 1 < NL) {
            combine_ln_k<true><<<SQ, 256>>>(ppart, b2 + l * EM, px, nullptr, phh,
                                            ln1_g + (l + 1) * EM, ln1_b + (l + 1) * EM);
        } else {
            combine_ln_k<false><<<SQ, 256>>>(ppart, b2 + l * EM, px, out, nullptr,
                                             lnf_g, lnf_b);
        }
    }
}

// round 14
// speedup vs baseline: 1.2913x; 1.2169x over previous
#include <cuda_runtime.h>
#include <cuda_fp16.h>
#include <math.h>
#include <stdint.h>

#define SQ   2048
#define EM   768
#define NH   12
#define DH   64
#define FFD  3072
#define NL   4
#define EPSF 1e-5f
#define NCHUNK 32

// GEMM tiling: BM=BN=128, BK=64 halves, 256 threads, warp tile 64x32
#define BM 128
#define BN 128
#define BK 64
#define RSTR 36            // smem row stride in u32 (32 used + 4 pad)
#define A_OFF 0
#define BH_OFF 4608
#define BL_OFF 9216
#define STAGE_U32 13824
#define SMEM_BYTES (2*STAGE_U32*4)   // 110592

// weight pool offsets (elements) — Wq,Wk,Wv,W1,W2 (Wo handled via N fusion)
#define WMAT   589824            // 768*768
#define W1MAT  2359296           // 768*3072
#define OFF_WQ 0
#define OFF_WK (4*WMAT)
#define OFF_WV (8*WMAT)
#define OFF_W1 (12*WMAT)
#define OFF_W2 (12*WMAT + 4*W1MAT)
#define WTOTAL (12*WMAT + 8*W1MAT)

// ---------------- scratch (no allocations allowed) ----------------
__device__ float g_x[SQ*EM];                 // residual stream (fp32)
__device__ float g_k[SQ*EM];                 // K (fp32)
__device__ float g_v[SQ*EM];                 // V (fp32)
__device__ float g_Mp[NH*NCHUNK*DH*DH];      // partial K^T V
__device__ float g_part[3*SQ*EM];            // split-K partials
__device__ __half g_qh[SQ*EM];               // Q (fp16)
__device__ __half g_h[SQ*EM];                // LN output (fp16)
__device__ __half g_ff[SQ*FFD];              // MLP hidden (fp16)
__device__ __half gwt_hi[WTOTAL];            // transposed weights hi
__device__ __half gwt_lo[WTOTAL];            // transposed weights lo (QKV only used)
__device__ __half g_nh[EM*EM];               // N = scale*M*Wo, transposed, hi
__device__ __half g_nl[EM*EM];               // N lo

// ---------------- helpers ----------------
__device__ __forceinline__ void mma_fp16(float c[4], const uint32_t a[4], const uint32_t b[2]) {
    asm volatile(
        "mma.sync.aligned.m16n8k16.row.col.f32.f16.f16.f32 "
        "{%0,%1,%2,%3},{%4,%5,%6,%7},{%8,%9},{%0,%1,%2,%3};\n"
        : "+f"(c[0]), "+f"(c[1]), "+f"(c[2]), "+f"(c[3])
        : "r"(a[0]), "r"(a[1]), "r"(a[2]), "r"(a[3]), "r"(b[0]), "r"(b[1]));
}
__device__ __forceinline__ void cpa16(uint32_t dst, const void* src) {
    asm volatile("cp.async.cg.shared.global [%0], [%1], 16;\n" :: "r"(dst), "l"(src) : "memory");
}
__device__ __forceinline__ void cp_commit() { asm volatile("cp.async.commit_group;\n" ::: "memory"); }
__device__ __forceinline__ void cp_wait1()  { asm volatile("cp.async.wait_group 1;\n" ::: "memory"); }
__device__ __forceinline__ void cp_wait0()  { asm volatile("cp.async.wait_group 0;\n" ::: "memory"); }

__device__ __forceinline__ void split_fp16(float v, __half& hi, __half& lo) {
    hi = __float2half_rn(v);
    lo = __float2half_rn(v - __half2float(hi));
}

// ---------------- weight transpose + split: src[L][K][N] -> dst[L][N][K] (hi,lo fp16) ----------------
template<bool QKV>
__global__ void wconv_k(const float* __restrict__ s0, const float* __restrict__ s1,
                        const float* __restrict__ s2,
                        __half* __restrict__ dhi, __half* __restrict__ dlo,
                        int K, int N, int poolStride) {
    __shared__ float t[32][33];
    int m = 0, l = blockIdx.z;
    if (QKV) { m = blockIdx.z / NL; l = blockIdx.z % NL; }
    const float* src = (m == 0) ? s0 : (m == 1) ? s1 : s2;
    const size_t lofs = (size_t)l * K * N;
    const size_t dofs = (size_t)m * 4 * WMAT + (size_t)l * poolStride;
    const int n0 = blockIdx.x * 32, k0 = blockIdx.y * 32;
    const int tx = threadIdx.x, ty = threadIdx.y;
    #pragma unroll
    for (int i = 0; i < 4; i++)
        t[ty + 8*i][tx] = src[lofs + (size_t)(k0 + ty + 8*i) * N + n0 + tx];
    __syncthreads();
    const int u = tx & 15, nx = tx >> 4;
    #pragma unroll
    for (int i = 0; i < 2; i++) {
        int n = ty + 8*i + 16*nx;
        float v0 = t[2*u][n], v1 = t[2*u + 1][n];
        __half h0, l0, h1, l1;
        split_fp16(v0, h0, l0);
        split_fp16(v1, h1, l1);
        size_t o = dofs + (size_t)(n0 + n) * K + k0 + 2*u;
        *reinterpret_cast<__half2*>(dhi + o) = __halves2half2(h0, h1);
        if (QKV)
            *reinterpret_cast<__half2*>(dlo + o) = __halves2half2(l0, l1);
    }
}

// ---------------- initial: x = emb + wpe, then LN -> fp16 ----------------
__global__ void __launch_bounds__(256)
addln_k(const float* __restrict__ emb, const float* __restrict__ wpe,
        float* __restrict__ px, __half* __restrict__ oh,
        const float* __restrict__ g, const float* __restrict__ b) {
    const int row = blockIdx.x;
    float loc[3];
    float s = 0.f, s2 = 0.f;
    #pragma unroll
    for (int t = 0; t < 3; t++) {
        int j = threadIdx.x + t * 256;
        size_t o = (size_t)row * EM + j;
        float v = emb[o] + wpe[o];
        px[o] = v;
        loc[t] = v;
        s += v; s2 += v * v;
    }
    __shared__ float rs[32], rs2[32];
    #pragma unroll
    for (int o = 16; o; o >>= 1) {
        s  += __shfl_down_sync(0xffffffffu, s,  o);
        s2 += __shfl_down_sync(0xffffffffu, s2, o);
    }
    int w = threadIdx.x >> 5, l = threadIdx.x & 31;
    if (l == 0) { rs[w] = s; rs2[w] = s2; }
    __syncthreads();
    if (w == 0) {
        s  = (l < 8) ? rs[l]  : 0.f;
        s2 = (l < 8) ? rs2[l] : 0.f;
        #pragma unroll
        for (int o = 4; o; o >>= 1) {
            s  += __shfl_down_sync(0xffffffffu, s,  o);
            s2 += __shfl_down_sync(0xffffffffu, s2, o);
        }
        if (l == 0) { rs[0] = s; rs2[0] = s2; }
    }
    __syncthreads();
    float mu  = rs[0] * (1.0f / EM);
    float var = rs2[0] * (1.0f / EM) - mu * mu;
    float inv = rsqrtf(var + EPSF);
    #pragma unroll
    for (int t = 0; t < 3; t++) {
        int j = threadIdx.x + t * 256;
        oh[(size_t)row * EM + j] = __float2half_rn((loc[t] - mu) * inv * g[j] + b[j]);
    }
}

// ---------------- combine 3 split-K partials + bias + residual, then LayerNorm ----------------
template<bool HALF>
__global__ void __launch_bounds__(256)
combine_ln_k(const float* __restrict__ parts, const float* __restrict__ bias,
             float* __restrict__ px, float* __restrict__ outf, __half* __restrict__ oh,
             const float* __restrict__ g, const float* __restrict__ b) {
    const int row = blockIdx.x;
    float loc[3];
    float s = 0.f, s2 = 0.f;
    #pragma unroll
    for (int t = 0; t < 3; t++) {
        int j = threadIdx.x + t * 256;
        size_t o = (size_t)row * EM + j;
        float v = px[o] + bias[j] + parts[o] + parts[o + (size_t)SQ*EM] + parts[o + 2*(size_t)SQ*EM];
        px[o] = v;
        loc[t] = v;
        s += v; s2 += v * v;
    }
    __shared__ float rs[32], rs2[32];
    #pragma unroll
    for (int o = 16; o; o >>= 1) {
        s  += __shfl_down_sync(0xffffffffu, s,  o);
        s2 += __shfl_down_sync(0xffffffffu, s2, o);
    }
    int w = threadIdx.x >> 5, l = threadIdx.x & 31;
    if (l == 0) { rs[w] = s; rs2[w] = s2; }
    __syncthreads();
    if (w == 0) {
        s  = (l < 8) ? rs[l]  : 0.f;
        s2 = (l < 8) ? rs2[l] : 0.f;
        #pragma unroll
        for (int o = 4; o; o >>= 1) {
            s  += __shfl_down_sync(0xffffffffu, s,  o);
            s2 += __shfl_down_sync(0xffffffffu, s2, o);
        }
        if (l == 0) { rs[0] = s; rs2[0] = s2; }
    }
    __syncthreads();
    float mu  = rs[0] * (1.0f / EM);
    float var = rs2[0] * (1.0f / EM) - mu * mu;
    float inv = rsqrtf(var + EPSF);
    #pragma unroll
    for (int t = 0; t < 3; t++) {
        int j = threadIdx.x + t * 256;
        float v = (loc[t] - mu) * inv * g[j] + b[j];
        if (HALF) oh[(size_t)row * EM + j] = __float2half_rn(v);
        else      outf[(size_t)row * EM + j] = v;
    }
}

// ---------------- fp16 tensor-core GEMM body (BK=64; TWOB: B hi+lo compensated) ----------------
// A (fp16, [M,Kfull] row-major), B (hi[/lo] fp16, [N,Kfull] k-major)
template<bool GELU, bool RES, bool OHALF, bool PART, bool TWOB>
__device__ __forceinline__ void gemm_body(
    const __half* __restrict__ Ah,
    const __half* __restrict__ Bh, const __half* __restrict__ Bl,
    const float* __restrict__ bias, const float* __restrict__ res,
    float* __restrict__ C, __half* __restrict__ Ch,
    int N, int Kfull, int kbase, int kcount, int row0, int col0, uint32_t* smem)
{
    const int tid  = threadIdx.x;
    const int lane = tid & 31, warp = tid >> 5;
    const int wm = warp >> 2, wn = warp & 3;   // 2 x 4 warp grid
    const int g = lane >> 2, q = lane & 3;

    uint32_t sbase = (uint32_t)__cvta_generic_to_shared(smem);

    float acc[4][4][4];
    #pragma unroll
    for (int i = 0; i < 4; i++)
        #pragma unroll
        for (int j = 0; j < 4; j++)
            #pragma unroll
            for (int t = 0; t < 4; t++) acc[i][j][t] = 0.f;

    const int KT = kcount / BK;

    auto load_tile = [&](int kt, int st) {
        uint32_t base = sbase + st * STAGE_U32 * 4;
        #pragma unroll
        for (int t = 0; t < 4; t++) {
            int chunk = tid + t * 256;             // 0..1023
            int r = chunk >> 3, c4 = (chunk & 7) * 4;
            size_t aoff = (size_t)(row0 + r) * Kfull + kbase + kt * BK + (chunk & 7) * 8;
            cpa16(base + (uint32_t)(A_OFF + r * RSTR + c4) * 4, Ah + aoff);
            size_t boff = (size_t)(col0 + r) * Kfull + kbase + kt * BK + (chunk & 7) * 8;
            cpa16(base + (uint32_t)(BH_OFF + r * RSTR + c4) * 4, Bh + boff);
            if (TWOB)
                cpa16(base + (uint32_t)(BL_OFF + r * RSTR + c4) * 4, Bl + boff);
        }
        cp_commit();
    };

    load_tile(0, 0);
    for (int kt = 0; kt < KT; kt++) {
        if (kt + 1 < KT) { load_tile(kt + 1, (kt + 1) & 1); cp_wait1(); }
        else             { cp_wait0(); }
        __syncthreads();

        const uint32_t* S = smem + (kt & 1) * STAGE_U32;

        #pragma unroll
        for (int ks = 0; ks < 4; ks++) {
            const int kq = ks * 8 + q;
            uint32_t af[4][4], bh[4][2], bl[4][2];
            #pragma unroll
            for (int mi = 0; mi < 4; mi++) {
                int rb = (wm * 64 + mi * 16 + g) * RSTR + kq;
                af[mi][0] = S[A_OFF + rb];       af[mi][1] = S[A_OFF + rb + 8*RSTR];
                af[mi][2] = S[A_OFF + rb + 4];   af[mi][3] = S[A_OFF + rb + 8*RSTR + 4];
            }
            #pragma unroll
            for (int ni = 0; ni < 4; ni++) {
                int nb = (wn * 32 + ni * 8 + g) * RSTR + kq;
                bh[ni][0] = S[BH_OFF + nb];  bh[ni][1] = S[BH_OFF + nb + 4];
                if (TWOB) {
                    bl[ni][0] = S[BL_OFF + nb];  bl[ni][1] = S[BL_OFF + nb + 4];
                }
            }
            #pragma unroll
            for (int mi = 0; mi < 4; mi++)
                #pragma unroll
                for (int ni = 0; ni < 4; ni++) {
                    if (TWOB) mma_fp16(acc[mi][ni], af[mi], bl[ni]);
                    mma_fp16(acc[mi][ni], af[mi], bh[ni]);
                }
        }
        __syncthreads();
    }

    // epilogue (C layout: t0=(g,2q) t1=(g,2q+1) t2=(g+8,2q) t3=(g+8,2q+1))
    #pragma unroll
    for (int mi = 0; mi < 4; mi++) {
        #pragma unroll
        for (int ni = 0; ni < 4; ni++) {
            int r0 = row0 + wm * 64 + mi * 16 + g;
            int c0 = col0 + wn * 32 + ni * 8 + 2 * q;
            float bb0 = PART ? 0.f : bias[c0];
            float bb1 = PART ? 0.f : bias[c0 + 1];
            #pragma unroll
            for (int h = 0; h < 2; h++) {
                int r = r0 + h * 8;
                float v0 = acc[mi][ni][2 * h]     + bb0;
                float v1 = acc[mi][ni][2 * h + 1] + bb1;
                if (GELU) {
                    v0 = 0.5f * v0 * (1.0f + erff(v0 * 0.70710678118654752f));
                    v1 = 0.5f * v1 * (1.0f + erff(v1 * 0.70710678118654752f));
                }
                if (RES) {
                    v0 += res[(size_t)r * N + c0];
                    v1 += res[(size_t)r * N + c0 + 1];
                }
                if (OHALF) {
                    Ch[(size_t)r * N + c0]     = __float2half_rn(v0);
                    Ch[(size_t)r * N + c0 + 1] = __float2half_rn(v1);
                } else {
                    C[(size_t)r * N + c0]     = v0;
                    C[(size_t)r * N + c0 + 1] = v1;
                }
            }
        }
    }
}

// W1: single-B-term GEMM + GELU -> fp16
__global__ void __launch_bounds__(256, 2)
gemm_w1(const __half* __restrict__ Ah, const __half* __restrict__ Bh,
        const float* __restrict__ bias, __half* __restrict__ Ch, int N, int K) {
    extern __shared__ uint32_t smem[];
    gemm_body<true, false, true, false, false>(Ah, Bh, nullptr, bias, nullptr, nullptr, Ch,
                                               N, K, 0, K, blockIdx.y * BM, blockIdx.x * BN, smem);
}

// split-K partial GEMM, 2-term B (O-projection)
__global__ void __launch_bounds__(256, 2)
gemm_part2_k(const __half* __restrict__ Ah,
             const __half* __restrict__ Bh, const __half* __restrict__ Bl,
             float* __restrict__ parts, int N, int Kfull, int ksplit) {
    extern __shared__ uint32_t smem[];
    float* Cp = parts + (size_t)blockIdx.z * SQ * N;
    gemm_body<false, false, false, true, true>(Ah, Bh, Bl, nullptr, nullptr, Cp, nullptr,
                                               N, Kfull, blockIdx.z * ksplit, ksplit,
                                               blockIdx.y * BM, blockIdx.x * BN, smem);
}

// split-K partial GEMM, single-term B (W2)
__global__ void __launch_bounds__(256, 2)
gemm_part1_k(const __half* __restrict__ Ah, const __half* __restrict__ Bh,
             float* __restrict__ parts, int N, int Kfull, int ksplit) {
    extern __shared__ uint32_t smem[];
    float* Cp = parts + (size_t)blockIdx.z * SQ * N;
    gemm_body<false, false, false, true, false>(Ah, Bh, nullptr, nullptr, nullptr, Cp, nullptr,
                                                N, Kfull, blockIdx.z * ksplit, ksplit,
                                                blockIdx.y * BM, blockIdx.x * BN, smem);
}

// K+V projection: grid.x = 2 * (EM/BN); outputs fp32 K and V (2-term B)
__global__ void __launch_bounds__(256, 2)
kv_tc(const __half* __restrict__ Bk_hi, const __half* __restrict__ Bk_lo,
      const __half* __restrict__ Bv_hi, const __half* __restrict__ Bv_lo,
      const float* __restrict__ bk, const float* __restrict__ bv) {
    extern __shared__ uint32_t smem[];
    const int nb = EM / BN;   // 6
    int m = blockIdx.x / nb, cb = blockIdx.x % nb;
    const __half* Bh = (m == 0) ? Bk_hi : Bv_hi;
    const __half* Bl = (m == 0) ? Bk_lo : Bv_lo;
    const float*  b  = (m == 0) ? bk : bv;
    float*        C  = (m == 0) ? g_k : g_v;
    gemm_body<false, false, false, false, true>(g_h, Bh, Bl, b, nullptr, C, nullptr,
                                                EM, EM, 0, EM, blockIdx.y * BM, cb * BN, smem);
}

// Q projection (side stream): outputs fp16 Q (2-term B)
__global__ void __launch_bounds__(256, 2)
q_tc(const __half* __restrict__ Bq_hi, const __half* __restrict__ Bq_lo,
     const float* __restrict__ bq) {
    extern __shared__ uint32_t smem[];
    gemm_body<false, false, true, false, true>(g_h, Bq_hi, Bq_lo, bq, nullptr, nullptr, g_qh,
                                               EM, EM, 0, EM, blockIdx.y * BM, blockIdx.x * BN, smem);
}

// ---------------- attention part 1: partial M = K_h^T V_h over an S-chunk ----------------
__global__ void __launch_bounds__(256) attn_m_k() {
    const int h = blockIdx.x, chunk = blockIdx.y;
    __shared__ float Ks[32][65];
    __shared__ float Vs[32][65];
    const int tid = threadIdx.x;
    const int tx = tid & 15, ty = tid >> 4;
    float acc[4][4] = {};
    const int sbase = chunk * (SQ / NCHUNK);
    for (int s0 = 0; s0 < SQ / NCHUNK; s0 += 32) {
        #pragma unroll
        for (int i = 0; i < 8; i++) {
            int idx = tid + i * 256;
            int r = idx >> 6, c = idx & 63;
            int gidx = (sbase + s0 + r) * EM + h * 64 + c;
            Ks[r][c] = g_k[gidx];
            Vs[r][c] = g_v[gidx];
        }
        __syncthreads();
        #pragma unroll
        for (int ss = 0; ss < 32; ss++) {
            float a[4], bb[4];
            #pragma unroll
            for (int i = 0; i < 4; i++) a[i]  = Ks[ss][ty + i * 16];
            #pragma unroll
            for (int j = 0; j < 4; j++) bb[j] = Vs[ss][tx + j * 16];
            #pragma unroll
            for (int i = 0; i < 4; i++)
                #pragma unroll
                for (int j = 0; j < 4; j++)
                    acc[i][j] += a[i] * bb[j];
        }
        __syncthreads();
    }
    #pragma unroll
    for (int i = 0; i < 4; i++)
        #pragma unroll
        for (int j = 0; j < 4; j++)
            g_Mp[((h * NCHUNK + chunk) * 64 + ty + i * 16) * 64 + tx + j * 16] = acc[i][j];
}

// ---------------- N = scale * M * Wo  (per head, transposed + split fp16) ----------------
__global__ void __launch_bounds__(256) nmat_k(const float* __restrict__ Wo) {
    const int h = blockIdx.x, ob = blockIdx.y;
    __shared__ float Ms[64][65];
    __shared__ float Ws[64][65];
    const int tid = threadIdx.x;
    #pragma unroll
    for (int i = 0; i < 16; i++) {
        int idx = tid + i * 256;
        int d1 = idx >> 6, d2 = idx & 63;
        float s = 0.f;
        #pragma unroll
        for (int c = 0; c < NCHUNK; c++)
            s += g_Mp[((h * NCHUNK + c) * 64 + d1) * 64 + d2];
        Ms[d1][d2] = s * 0.125f;   // DH^-0.5
        int e = idx >> 6, o = idx & 63;
        Ws[e][o] = Wo[(size_t)(h * 64 + e) * EM + ob * 64 + o];
    }
    __syncthreads();
    const int o = tid & 63, dbase = (tid >> 6) * 16;
    #pragma unroll
    for (int dd = 0; dd < 16; dd++) {
        int d = dbase + dd;
        float s = 0.f;
        #pragma unroll
        for (int e = 0; e < 64; e++)
            s += Ms[d][e] * Ws[e][o];
        __half hi, lo;
        split_fp16(s, hi, lo);
        size_t off = (size_t)(ob * 64 + o) * EM + h * 64 + d;
        g_nh[off] = hi;
        g_nl[off] = lo;
    }
}

// ---------------- host ----------------
extern "C" void kernel_launch(void* const* d_in, const int* in_sizes, int n_in,
                              void* d_out, int out_size) {
    const float* emb   = (const float*)d_in[0];
    const float* wpe   = (const float*)d_in[1];
    const float* ln1_g = (const float*)d_in[2];
    const float* ln1_b = (const float*)d_in[3];
    const float* Wq    = (const float*)d_in[4];
    const float* bq    = (const float*)d_in[5];
    const float* Wk    = (const float*)d_in[6];
    const float* bk    = (const float*)d_in[7];
    const float* Wv    = (const float*)d_in[8];
    const float* bv    = (const float*)d_in[9];
    const float* Wo    = (const float*)d_in[10];
    const float* bo    = (const float*)d_in[11];
    const float* ln2_g = (const float*)d_in[12];
    const float* ln2_b = (const float*)d_in[13];
    const float* W1    = (const float*)d_in[14];
    const float* b1    = (const float*)d_in[15];
    const float* W2    = (const float*)d_in[16];
    const float* b2    = (const float*)d_in[17];
    const float* lnf_g = (const float*)d_in[18];
    const float* lnf_b = (const float*)d_in[19];
    float* out = (float*)d_out;

    float *px, *ppart;
    __half *pwh, *pwl, *pnh, *pnl, *pqh, *phh, *pff;
    cudaGetSymbolAddress((void**)&px,    g_x);
    cudaGetSymbolAddress((void**)&ppart, g_part);
    cudaGetSymbolAddress((void**)&pwh,   gwt_hi);
    cudaGetSymbolAddress((void**)&pwl,   gwt_lo);
    cudaGetSymbolAddress((void**)&pnh,   g_nh);
    cudaGetSymbolAddress((void**)&pnl,   g_nl);
    cudaGetSymbolAddress((void**)&pqh,   g_qh);
    cudaGetSymbolAddress((void**)&phh,   g_h);
    cudaGetSymbolAddress((void**)&pff,   g_ff);

    cudaFuncSetAttribute(gemm_w1,
                         cudaFuncAttributeMaxDynamicSharedMemorySize, SMEM_BYTES);
    cudaFuncSetAttribute(gemm_part2_k,
                         cudaFuncAttributeMaxDynamicSharedMemorySize, SMEM_BYTES);
    cudaFuncSetAttribute(gemm_part1_k,
                         cudaFuncAttributeMaxDynamicSharedMemorySize, SMEM_BYTES);
    cudaFuncSetAttribute(kv_tc,
                         cudaFuncAttributeMaxDynamicSharedMemorySize, SMEM_BYTES);
    cudaFuncSetAttribute(q_tc,
                         cudaFuncAttributeMaxDynamicSharedMemorySize, SMEM_BYTES);

    // side stream + fork/join events (host objects; created once, no device memory)
    static cudaStream_t s2 = nullptr;
    static cudaEvent_t evF = nullptr, evQ = nullptr, evW = nullptr;
    if (!s2) {
        cudaStreamCreateWithFlags(&s2, cudaStreamNonBlocking);
        cudaEventCreateWithFlags(&evF, cudaEventDisableTiming);
        cudaEventCreateWithFlags(&evQ, cudaEventDisableTiming);
        cudaEventCreateWithFlags(&evW, cudaEventDisableTiming);
    }

    dim3 wblk(32, 8);

    // fork: W1/W2 weight conversion on side stream (hi only)
    cudaEventRecord(evF, 0);
    cudaStreamWaitEvent(s2, evF, 0);
    wconv_k<false><<<dim3(FFD/32, EM/32,  NL), wblk, 0, s2>>>(
        W1, nullptr, nullptr, pwh + OFF_W1, nullptr, EM,  FFD, W1MAT);
    wconv_k<false><<<dim3(EM/32,  FFD/32, NL), wblk, 0, s2>>>(
        W2, nullptr, nullptr, pwh + OFF_W2, nullptr, FFD, EM,  W1MAT);
    cudaEventRecord(evW, s2);

    // main stream: QKV weight conversion + initial add+LN
    wconv_k<true><<<dim3(EM/32, EM/32, 3*NL), wblk>>>(
        Wq, Wk, Wv, pwh + OFF_WQ, pwl + OFF_WQ, EM, EM, WMAT);
    addln_k<<<SQ, 256>>>(emb, wpe, px, phh, ln1_g, ln1_b);

    const dim3 gKV(2 * (EM / BN), SQ / BM);      // (12, 16)
    const dim3 gQ(EM / BN, SQ / BM);             // (6, 16)
    const dim3 gS(EM / BN, SQ / BM, 3);          // split-K grids (6, 16, 3)
    const dim3 gF(FFD / BN, SQ / BM);            // (24, 16)

    for (int l = 0; l < NL; l++) {
        const __half* wq_h = pwh + OFF_WQ + (size_t)l * WMAT;
        const __half* wq_l = pwl + OFF_WQ + (size_t)l * WMAT;
        const __half* wk_h = pwh + OFF_WK + (size_t)l * WMAT;
        const __half* wk_l = pwl + OFF_WK + (size_t)l * WMAT;
        const __half* wv_h = pwh + OFF_WV + (size_t)l * WMAT;
        const __half* wv_l = pwl + OFF_WV + (size_t)l * WMAT;
        const __half* w1_h = pwh + OFF_W1 + (size_t)l * W1MAT;
        const __half* w2_h = pwh + OFF_W2 + (size_t)l * W1MAT;

        // fork: Q projection on side stream, concurrent with KV + attn_m + nmat
        cudaEventRecord(evF, 0);
        cudaStreamWaitEvent(s2, evF, 0);
        q_tc<<<gQ, 256, SMEM_BYTES, s2>>>(wq_h, wq_l, bq + l * EM);
        cudaEventRecord(evQ, s2);

        kv_tc<<<gKV, 256, SMEM_BYTES>>>(wk_h, wk_l, wv_h, wv_l, bk + l * EM, bv + l * EM);
        attn_m_k<<<dim3(NH, NCHUNK), 256>>>();
        nmat_k<<<dim3(NH, EM / 64), 256>>>(Wo + (size_t)l * EM * EM);

        // join: O-projection needs Q (2-term B)
        cudaStreamWaitEvent(0, evQ, 0);
        gemm_part2_k<<<gS, 256, SMEM_BYTES>>>(pqh, pnh, pnl, ppart, EM, EM, EM / 3);
        combine_ln_k<true><<<SQ, 256>>>(ppart, bo + l * EM, px, nullptr, phh,
                                        ln2_g + l * EM, ln2_b + l * EM);

        // join: first W1 use must wait for side-stream weight conversion
        if (l == 0) cudaStreamWaitEvent(0, evW, 0);
        gemm_w1<<<gF, 256, SMEM_BYTES>>>(phh, w1_h, b1 + l * FFD, pff, FFD, EM);

        // W2: split-K=3 single-term, combine + next LN fused
        gemm_part1_k<<<gS, 256, SMEM_BYTES>>>(pff, w2_h, ppart, EM, FFD, FFD / 3);
        if (l + 1 < NL) {
            combine_ln_k<true><<<SQ, 256>>>(ppart, b2 + l * EM, px, nullptr, phh,
                                            ln1_g + (l + 1) * EM, ln1_b + (l + 1) * EM);
        } else {
            combine_ln_k<false><<<SQ, 256>>>(ppart, b2 + l * EM, px, out, nullptr,
                                             lnf_g, lnf_b);
        }
    }
}

// round 16
// speedup vs baseline: 1.3658x; 1.0577x over previous
#include <cuda_runtime.h>
#include <cuda_fp16.h>
#include <math.h>
#include <stdint.h>

#define SQ   2048
#define EM   768
#define NH   12
#define DH   64
#define FFD  3072
#define NL   4
#define EPSF 1e-5f
#define NCHUNK 32

// GEMM tiling: BM=BN=128, BK=64 halves, 256 threads, warp tile 64x32
#define BM 128
#define BN 128
#define BK 64
#define RSTR 36            // smem row stride in u32 (32 used + 4 pad)
#define A_OFF 0
#define BH_OFF 4608
#define BL_OFF 9216
#define STAGE_U32 13824
#define SMEM_BYTES (2*STAGE_U32*4)   // 110592

// weight pool offsets (elements) — Wq,Wk,Wv,W1,W2 (Wo handled via N fusion)
#define WMAT   589824            // 768*768
#define W1MAT  2359296           // 768*3072
#define OFF_WQ 0
#define OFF_WK (4*WMAT)
#define OFF_WV (8*WMAT)
#define OFF_W1 (12*WMAT)
#define OFF_W2 (12*WMAT + 4*W1MAT)
#define WTOTAL (12*WMAT + 8*W1MAT)

// ---------------- scratch (no allocations allowed) ----------------
__device__ float g_x[SQ*EM];                 // residual stream (fp32)
__device__ float g_k[SQ*EM];                 // K (fp32)
__device__ float g_v[SQ*EM];                 // V (fp32)
__device__ float g_Mp[NH*NCHUNK*DH*DH];      // partial K^T V
__device__ float g_part[3*SQ*EM];            // split-K partials
__device__ __half g_qh[SQ*EM];               // Q (fp16)
__device__ __half g_h[SQ*EM];                // LN output (fp16)
__device__ __half g_ff[SQ*FFD];              // MLP hidden (fp16)
__device__ __half gwt_hi[WTOTAL];            // transposed weights hi
__device__ __half gwt_lo[WTOTAL];            // transposed weights lo (Q/K/V used)
__device__ __half g_nh[EM*EM];               // N = scale*M*Wo, transposed (fp16)

// ---------------- helpers ----------------
__device__ __forceinline__ void mma_fp16(float c[4], const uint32_t a[4], const uint32_t b[2]) {
    asm volatile(
        "mma.sync.aligned.m16n8k16.row.col.f32.f16.f16.f32 "
        "{%0,%1,%2,%3},{%4,%5,%6,%7},{%8,%9},{%0,%1,%2,%3};\n"
        : "+f"(c[0]), "+f"(c[1]), "+f"(c[2]), "+f"(c[3])
        : "r"(a[0]), "r"(a[1]), "r"(a[2]), "r"(a[3]), "r"(b[0]), "r"(b[1]));
}
__device__ __forceinline__ void cpa16(uint32_t dst, const void* src) {
    asm volatile("cp.async.cg.shared.global [%0], [%1], 16;\n" :: "r"(dst), "l"(src) : "memory");
}
__device__ __forceinline__ void cp_commit() { asm volatile("cp.async.commit_group;\n" ::: "memory"); }
__device__ __forceinline__ void cp_wait1()  { asm volatile("cp.async.wait_group 1;\n" ::: "memory"); }
__device__ __forceinline__ void cp_wait0()  { asm volatile("cp.async.wait_group 0;\n" ::: "memory"); }

__device__ __forceinline__ void split_fp16(float v, __half& hi, __half& lo) {
    hi = __float2half_rn(v);
    lo = __float2half_rn(v - __half2float(hi));
}

// ---------------- weight transpose + split: src[L][K][N] -> dst[L][N][K] (hi[,lo] fp16) ----------------
template<bool QKV>
__global__ void wconv_k(const float* __restrict__ s0, const float* __restrict__ s1,
                        const float* __restrict__ s2,
                        __half* __restrict__ dhi, __half* __restrict__ dlo,
                        int K, int N, int poolStride) {
    __shared__ float t[32][33];
    int m = 0, l = blockIdx.z;
    if (QKV) { m = blockIdx.z / NL; l = blockIdx.z % NL; }
    const float* src = (m == 0) ? s0 : (m == 1) ? s1 : s2;
    const size_t lofs = (size_t)l * K * N;
    const size_t dofs = (size_t)m * 4 * WMAT + (size_t)l * poolStride;
    const int n0 = blockIdx.x * 32, k0 = blockIdx.y * 32;
    const int tx = threadIdx.x, ty = threadIdx.y;
    #pragma unroll
    for (int i = 0; i < 4; i++)
        t[ty + 8*i][tx] = src[lofs + (size_t)(k0 + ty + 8*i) * N + n0 + tx];
    __syncthreads();
    const int u = tx & 15, nx = tx >> 4;
    #pragma unroll
    for (int i = 0; i < 2; i++) {
        int n = ty + 8*i + 16*nx;
        float v0 = t[2*u][n], v1 = t[2*u + 1][n];
        __half h0, l0, h1, l1;
        split_fp16(v0, h0, l0);
        split_fp16(v1, h1, l1);
        size_t o = dofs + (size_t)(n0 + n) * K + k0 + 2*u;
        *reinterpret_cast<__half2*>(dhi + o) = __halves2half2(h0, h1);
        if (QKV)   // lo kept for Q, K, V weights
            *reinterpret_cast<__half2*>(dlo + o) = __halves2half2(l0, l1);
    }
}

// ---------------- initial: x = emb + wpe, then LN -> fp16 ----------------
__global__ void __launch_bounds__(256)
addln_k(const float* __restrict__ emb, const float* __restrict__ wpe,
        float* __restrict__ px, __half* __restrict__ oh,
        const float* __restrict__ g, const float* __restrict__ b) {
    const int row = blockIdx.x;
    float loc[3];
    float s = 0.f, s2 = 0.f;
    #pragma unroll
    for (int t = 0; t < 3; t++) {
        int j = threadIdx.x + t * 256;
        size_t o = (size_t)row * EM + j;
        float v = emb[o] + wpe[o];
        px[o] = v;
        loc[t] = v;
        s += v; s2 += v * v;
    }
    __shared__ float rs[32], rs2[32];
    #pragma unroll
    for (int o = 16; o; o >>= 1) {
        s  += __shfl_down_sync(0xffffffffu, s,  o);
        s2 += __shfl_down_sync(0xffffffffu, s2, o);
    }
    int w = threadIdx.x >> 5, l = threadIdx.x & 31;
    if (l == 0) { rs[w] = s; rs2[w] = s2; }
    __syncthreads();
    if (w == 0) {
        s  = (l < 8) ? rs[l]  : 0.f;
        s2 = (l < 8) ? rs2[l] : 0.f;
        #pragma unroll
        for (int o = 4; o; o >>= 1) {
            s  += __shfl_down_sync(0xffffffffu, s,  o);
            s2 += __shfl_down_sync(0xffffffffu, s2, o);
        }
        if (l == 0) { rs[0] = s; rs2[0] = s2; }
    }
    __syncthreads();
    float mu  = rs[0] * (1.0f / EM);
    float var = rs2[0] * (1.0f / EM) - mu * mu;
    float inv = rsqrtf(var + EPSF);
    #pragma unroll
    for (int t = 0; t < 3; t++) {
        int j = threadIdx.x + t * 256;
        oh[(size_t)row * EM + j] = __float2half_rn((loc[t] - mu) * inv * g[j] + b[j]);
    }
}

// ---------------- combine 3 split-K partials + bias + residual, then LayerNorm ----------------
template<bool HALF>
__global__ void __launch_bounds__(256)
combine_ln_k(const float* __restrict__ parts, const float* __restrict__ bias,
             float* __restrict__ px, float* __restrict__ outf, __half* __restrict__ oh,
             const float* __restrict__ g, const float* __restrict__ b) {
    const int row = blockIdx.x;
    float loc[3];
    float s = 0.f, s2 = 0.f;
    #pragma unroll
    for (int t = 0; t < 3; t++) {
        int j = threadIdx.x + t * 256;
        size_t o = (size_t)row * EM + j;
        float v = px[o] + bias[j] + parts[o] + parts[o + (size_t)SQ*EM] + parts[o + 2*(size_t)SQ*EM];
        px[o] = v;
        loc[t] = v;
        s += v; s2 += v * v;
    }
    __shared__ float rs[32], rs2[32];
    #pragma unroll
    for (int o = 16; o; o >>= 1) {
        s  += __shfl_down_sync(0xffffffffu, s,  o);
        s2 += __shfl_down_sync(0xffffffffu, s2, o);
    }
    int w = threadIdx.x >> 5, l = threadIdx.x & 31;
    if (l == 0) { rs[w] = s; rs2[w] = s2; }
    __syncthreads();
    if (w == 0) {
        s  = (l < 8) ? rs[l]  : 0.f;
        s2 = (l < 8) ? rs2[l] : 0.f;
        #pragma unroll
        for (int o = 4; o; o >>= 1) {
            s  += __shfl_down_sync(0xffffffffu, s,  o);
            s2 += __shfl_down_sync(0xffffffffu, s2, o);
        }
        if (l == 0) { rs[0] = s; rs2[0] = s2; }
    }
    __syncthreads();
    float mu  = rs[0] * (1.0f / EM);
    float var = rs2[0] * (1.0f / EM) - mu * mu;
    float inv = rsqrtf(var + EPSF);
    #pragma unroll
    for (int t = 0; t < 3; t++) {
        int j = threadIdx.x + t * 256;
        float v = (loc[t] - mu) * inv * g[j] + b[j];
        if (HALF) oh[(size_t)row * EM + j] = __float2half_rn(v);
        else      outf[(size_t)row * EM + j] = v;
    }
}

// ---------------- fp16 tensor-core GEMM body (BK=64; TWOB: B hi+lo compensated) ----------------
// A (fp16, [M,Kfull] row-major), B (hi[/lo] fp16, [N,Kfull] k-major)
template<bool GELU, bool RES, bool OHALF, bool PART, bool TWOB>
__device__ __forceinline__ void gemm_body(
    const __half* __restrict__ Ah,
    const __half* __restrict__ Bh, const __half* __restrict__ Bl,
    const float* __restrict__ bias, const float* __restrict__ res,
    float* __restrict__ C, __half* __restrict__ Ch,
    int N, int Kfull, int kbase, int kcount, int row0, int col0, uint32_t* smem)
{
    const int tid  = threadIdx.x;
    const int lane = tid & 31, warp = tid >> 5;
    const int wm = warp >> 2, wn = warp & 3;   // 2 x 4 warp grid
    const int g = lane >> 2, q = lane & 3;

    uint32_t sbase = (uint32_t)__cvta_generic_to_shared(smem);

    float acc[4][4][4];
    #pragma unroll
    for (int i = 0; i < 4; i++)
        #pragma unroll
        for (int j = 0; j < 4; j++)
            #pragma unroll
            for (int t = 0; t < 4; t++) acc[i][j][t] = 0.f;

    const int KT = kcount / BK;

    auto load_tile = [&](int kt, int st) {
        uint32_t base = sbase + st * STAGE_U32 * 4;
        #pragma unroll
        for (int t = 0; t < 4; t++) {
            int chunk = tid + t * 256;             // 0..1023
            int r = chunk >> 3, c4 = (chunk & 7) * 4;
            size_t aoff = (size_t)(row0 + r) * Kfull + kbase + kt * BK + (chunk & 7) * 8;
            cpa16(base + (uint32_t)(A_OFF + r * RSTR + c4) * 4, Ah + aoff);
            size_t boff = (size_t)(col0 + r) * Kfull + kbase + kt * BK + (chunk & 7) * 8;
            cpa16(base + (uint32_t)(BH_OFF + r * RSTR + c4) * 4, Bh + boff);
            if (TWOB)
                cpa16(base + (uint32_t)(BL_OFF + r * RSTR + c4) * 4, Bl + boff);
        }
        cp_commit();
    };

    load_tile(0, 0);
    for (int kt = 0; kt < KT; kt++) {
        if (kt + 1 < KT) { load_tile(kt + 1, (kt + 1) & 1); cp_wait1(); }
        else             { cp_wait0(); }
        __syncthreads();

        const uint32_t* S = smem + (kt & 1) * STAGE_U32;

        #pragma unroll
        for (int ks = 0; ks < 4; ks++) {
            const int kq = ks * 8 + q;
            uint32_t af[4][4], bh[4][2], bl[4][2];
            #pragma unroll
            for (int mi = 0; mi < 4; mi++) {
                int rb = (wm * 64 + mi * 16 + g) * RSTR + kq;
                af[mi][0] = S[A_OFF + rb];       af[mi][1] = S[A_OFF + rb + 8*RSTR];
                af[mi][2] = S[A_OFF + rb + 4];   af[mi][3] = S[A_OFF + rb + 8*RSTR + 4];
            }
            #pragma unroll
            for (int ni = 0; ni < 4; ni++) {
                int nb = (wn * 32 + ni * 8 + g) * RSTR + kq;
                bh[ni][0] = S[BH_OFF + nb];  bh[ni][1] = S[BH_OFF + nb + 4];
                if (TWOB) {
                    bl[ni][0] = S[BL_OFF + nb];  bl[ni][1] = S[BL_OFF + nb + 4];
                }
            }
            #pragma unroll
            for (int mi = 0; mi < 4; mi++)
                #pragma unroll
                for (int ni = 0; ni < 4; ni++) {
                    if (TWOB) mma_fp16(acc[mi][ni], af[mi], bl[ni]);
                    mma_fp16(acc[mi][ni], af[mi], bh[ni]);
                }
        }
        __syncthreads();
    }

    // epilogue (C layout: t0=(g,2q) t1=(g,2q+1) t2=(g+8,2q) t3=(g+8,2q+1))
    #pragma unroll
    for (int mi = 0; mi < 4; mi++) {
        #pragma unroll
        for (int ni = 0; ni < 4; ni++) {
            int r0 = row0 + wm * 64 + mi * 16 + g;
            int c0 = col0 + wn * 32 + ni * 8 + 2 * q;
            float bb0 = PART ? 0.f : bias[c0];
            float bb1 = PART ? 0.f : bias[c0 + 1];
            #pragma unroll
            for (int h = 0; h < 2; h++) {
                int r = r0 + h * 8;
                float v0 = acc[mi][ni][2 * h]     + bb0;
                float v1 = acc[mi][ni][2 * h + 1] + bb1;
                if (GELU) {
                    v0 = 0.5f * v0 * (1.0f + erff(v0 * 0.70710678118654752f));
                    v1 = 0.5f * v1 * (1.0f + erff(v1 * 0.70710678118654752f));
                }
                if (RES) {
                    v0 += res[(size_t)r * N + c0];
                    v1 += res[(size_t)r * N + c0 + 1];
                }
                if (OHALF) {
                    Ch[(size_t)r * N + c0]     = __float2half_rn(v0);
                    Ch[(size_t)r * N + c0 + 1] = __float2half_rn(v1);
                } else {
                    C[(size_t)r * N + c0]     = v0;
                    C[(size_t)r * N + c0 + 1] = v1;
                }
            }
        }
    }
}

// W1: single-B-term GEMM + GELU -> fp16
__global__ void __launch_bounds__(256, 2)
gemm_w1(const __half* __restrict__ Ah, const __half* __restrict__ Bh,
        const float* __restrict__ bias, __half* __restrict__ Ch, int N, int K) {
    extern __shared__ uint32_t smem[];
    gemm_body<true, false, true, false, false>(Ah, Bh, nullptr, bias, nullptr, nullptr, Ch,
                                               N, K, 0, K, blockIdx.y * BM, blockIdx.x * BN, smem);
}

// split-K partial GEMM, single-term B (O-projection and W2)
__global__ void __launch_bounds__(256, 2)
gemm_part1_k(const __half* __restrict__ Ah, const __half* __restrict__ Bh,
             float* __restrict__ parts, int N, int Kfull, int ksplit) {
    extern __shared__ uint32_t smem[];
    float* Cp = parts + (size_t)blockIdx.z * SQ * N;
    gemm_body<false, false, false, true, false>(Ah, Bh, nullptr, nullptr, nullptr, Cp, nullptr,
                                                N, Kfull, blockIdx.z * ksplit, ksplit,
                                                blockIdx.y * BM, blockIdx.x * BN, smem);
}

// K+V projection: grid.x = 2 * (EM/BN); outputs fp32 K and V (2-term B)
__global__ void __launch_bounds__(256, 2)
kv_tc(const __half* __restrict__ Bk_hi, const __half* __restrict__ Bk_lo,
      const __half* __restrict__ Bv_hi, const __half* __restrict__ Bv_lo,
      const float* __restrict__ bk, const float* __restrict__ bv) {
    extern __shared__ uint32_t smem[];
    const int nb = EM / BN;   // 6
    int m = blockIdx.x / nb, cb = blockIdx.x % nb;
    const __half* Bh = (m == 0) ? Bk_hi : Bv_hi;
    const __half* Bl = (m == 0) ? Bk_lo : Bv_lo;
    const float*  b  = (m == 0) ? bk : bv;
    float*        C  = (m == 0) ? g_k : g_v;
    gemm_body<false, false, false, false, true>(g_h, Bh, Bl, b, nullptr, C, nullptr,
                                                EM, EM, 0, EM, blockIdx.y * BM, cb * BN, smem);
}

// Q projection (side stream, hidden): outputs fp16 Q (2-term B)
__global__ void __launch_bounds__(256, 2)
q_tc(const __half* __restrict__ Bq_hi, const __half* __restrict__ Bq_lo,
     const float* __restrict__ bq) {
    extern __shared__ uint32_t smem[];
    gemm_body<false, false, true, false, true>(g_h, Bq_hi, Bq_lo, bq, nullptr, nullptr, g_qh,
                                               EM, EM, 0, EM, blockIdx.y * BM, blockIdx.x * BN, smem);
}

// ---------------- attention part 1: partial M = K_h^T V_h over an S-chunk ----------------
__global__ void __launch_bounds__(256) attn_m_k() {
    const int h = blockIdx.x, chunk = blockIdx.y;
    __shared__ float Ks[32][65];
    __shared__ float Vs[32][65];
    const int tid = threadIdx.x;
    const int tx = tid & 15, ty = tid >> 4;
    float acc[4][4] = {};
    const int sbase = chunk * (SQ / NCHUNK);
    for (int s0 = 0; s0 < SQ / NCHUNK; s0 += 32) {
        #pragma unroll
        for (int i = 0; i < 8; i++) {
            int idx = tid + i * 256;
            int r = idx >> 6, c = idx & 63;
            int gidx = (sbase + s0 + r) * EM + h * 64 + c;
            Ks[r][c] = g_k[gidx];
            Vs[r][c] = g_v[gidx];
        }
        __syncthreads();
        #pragma unroll
        for (int ss = 0; ss < 32; ss++) {
            float a[4], bb[4];
            #pragma unroll
            for (int i = 0; i < 4; i++) a[i]  = Ks[ss][ty + i * 16];
            #pragma unroll
            for (int j = 0; j < 4; j++) bb[j] = Vs[ss][tx + j * 16];
            #pragma unroll
            for (int i = 0; i < 4; i++)
                #pragma unroll
                for (int j = 0; j < 4; j++)
                    acc[i][j] += a[i] * bb[j];
        }
        __syncthreads();
    }
    #pragma unroll
    for (int i = 0; i < 4; i++)
        #pragma unroll
        for (int j = 0; j < 4; j++)
            g_Mp[((h * NCHUNK + chunk) * 64 + ty + i * 16) * 64 + tx + j * 16] = acc[i][j];
}

// ---------------- N = scale * M * Wo  (per head, transposed fp16) ----------------
__global__ void __launch_bounds__(256) nmat_k(const float* __restrict__ Wo) {
    const int h = blockIdx.x, ob = blockIdx.y;
    __shared__ float Ms[64][65];
    __shared__ float Ws[64][65];
    const int tid = threadIdx.x;
    #pragma unroll
    for (int i = 0; i < 16; i++) {
        int idx = tid + i * 256;
        int d1 = idx >> 6, d2 = idx & 63;
        float s = 0.f;
        #pragma unroll
        for (int c = 0; c < NCHUNK; c++)
            s += g_Mp[((h * NCHUNK + c) * 64 + d1) * 64 + d2];
        Ms[d1][d2] = s * 0.125f;   // DH^-0.5
        int e = idx >> 6, o = idx & 63;
        Ws[e][o] = Wo[(size_t)(h * 64 + e) * EM + ob * 64 + o];
    }
    __syncthreads();
    const int o = tid & 63, dbase = (tid >> 6) * 16;
    #pragma unroll
    for (int dd = 0; dd < 16; dd++) {
        int d = dbase + dd;
        float s = 0.f;
        #pragma unroll
        for (int e = 0; e < 64; e++)
            s += Ms[d][e] * Ws[e][o];
        g_nh[(size_t)(ob * 64 + o) * EM + h * 64 + d] = __float2half_rn(s);
    }
}

// ---------------- host ----------------
extern "C" void kernel_launch(void* const* d_in, const int* in_sizes, int n_in,
                              void* d_out, int out_size) {
    const float* emb   = (const float*)d_in[0];
    const float* wpe   = (const float*)d_in[1];
    const float* ln1_g = (const float*)d_in[2];
    const float* ln1_b = (const float*)d_in[3];
    const float* Wq    = (const float*)d_in[4];
    const float* bq    = (const float*)d_in[5];
    const float* Wk    = (const float*)d_in[6];
    const float* bk    = (const float*)d_in[7];
    const float* Wv    = (const float*)d_in[8];
    const float* bv    = (const float*)d_in[9];
    const float* Wo    = (const float*)d_in[10];
    const float* bo    = (const float*)d_in[11];
    const float* ln2_g = (const float*)d_in[12];
    const float* ln2_b = (const float*)d_in[13];
    const float* W1    = (const float*)d_in[14];
    const float* b1    = (const float*)d_in[15];
    const float* W2    = (const float*)d_in[16];
    const float* b2    = (const float*)d_in[17];
    const float* lnf_g = (const float*)d_in[18];
    const float* lnf_b = (const float*)d_in[19];
    float* out = (float*)d_out;

    float *px, *ppart;
    __half *pwh, *pwl, *pnh, *pqh, *phh, *pff;
    cudaGetSymbolAddress((void**)&px,    g_x);
    cudaGetSymbolAddress((void**)&ppart, g_part);
    cudaGetSymbolAddress((void**)&pwh,   gwt_hi);
    cudaGetSymbolAddress((void**)&pwl,   gwt_lo);
    cudaGetSymbolAddress((void**)&pnh,   g_nh);
    cudaGetSymbolAddress((void**)&pqh,   g_qh);
    cudaGetSymbolAddress((void**)&phh,   g_h);
    cudaGetSymbolAddress((void**)&pff,   g_ff);

    cudaFuncSetAttribute(gemm_w1,
                         cudaFuncAttributeMaxDynamicSharedMemorySize, SMEM_BYTES);
    cudaFuncSetAttribute(gemm_part1_k,
                         cudaFuncAttributeMaxDynamicSharedMemorySize, SMEM_BYTES);
    cudaFuncSetAttribute(kv_tc,
                         cudaFuncAttributeMaxDynamicSharedMemorySize, SMEM_BYTES);
    cudaFuncSetAttribute(q_tc,
                         cudaFuncAttributeMaxDynamicSharedMemorySize, SMEM_BYTES);

    // side stream + fork/join events (host objects; created once, no device memory)
    static cudaStream_t s2 = nullptr;
    static cudaEvent_t evF = nullptr, evQ = nullptr, evW = nullptr;
    if (!s2) {
        cudaStreamCreateWithFlags(&s2, cudaStreamNonBlocking);
        cudaEventCreateWithFlags(&evF, cudaEventDisableTiming);
        cudaEventCreateWithFlags(&evQ, cudaEventDisableTiming);
        cudaEventCreateWithFlags(&evW, cudaEventDisableTiming);
    }

    dim3 wblk(32, 8);

    // fork: W1/W2 weight conversion on side stream (hi only)
    cudaEventRecord(evF, 0);
    cudaStreamWaitEvent(s2, evF, 0);
    wconv_k<false><<<dim3(FFD/32, EM/32,  NL), wblk, 0, s2>>>(
        W1, nullptr, nullptr, pwh + OFF_W1, nullptr, EM,  FFD, W1MAT);
    wconv_k<false><<<dim3(EM/32,  FFD/32, NL), wblk, 0, s2>>>(
        W2, nullptr, nullptr, pwh + OFF_W2, nullptr, FFD, EM,  W1MAT);
    cudaEventRecord(evW, s2);

    // main stream: QKV weight conversion + initial add+LN
    wconv_k<true><<<dim3(EM/32, EM/32, 3*NL), wblk>>>(
        Wq, Wk, Wv, pwh + OFF_WQ, pwl + OFF_WQ, EM, EM, WMAT);
    addln_k<<<SQ, 256>>>(emb, wpe, px, phh, ln1_g, ln1_b);

    const dim3 gKV(2 * (EM / BN), SQ / BM);      // (12, 16)
    const dim3 gQ(EM / BN, SQ / BM);             // (6, 16)
    const dim3 gS(EM / BN, SQ / BM, 3);          // split-K grids (6, 16, 3)
    const dim3 gF(FFD / BN, SQ / BM);            // (24, 16)

    for (int l = 0; l < NL; l++) {
        const __half* wq_h = pwh + OFF_WQ + (size_t)l * WMAT;
        const __half* wq_l = pwl + OFF_WQ + (size_t)l * WMAT;
        const __half* wk_h = pwh + OFF_WK + (size_t)l * WMAT;
        const __half* wk_l = pwl + OFF_WK + (size_t)l * WMAT;
        const __half* wv_h = pwh + OFF_WV + (size_t)l * WMAT;
        const __half* wv_l = pwl + OFF_WV + (size_t)l * WMAT;
        const __half* w1_h = pwh + OFF_W1 + (size_t)l * W1MAT;
        const __half* w2_h = pwh + OFF_W2 + (size_t)l * W1MAT;

        // fork: Q projection (2-term, hidden) on side stream
        cudaEventRecord(evF, 0);
        cudaStreamWaitEvent(s2, evF, 0);
        q_tc<<<gQ, 256, SMEM_BYTES, s2>>>(wq_h, wq_l, bq + l * EM);
        cudaEventRecord(evQ, s2);

        kv_tc<<<gKV, 256, SMEM_BYTES>>>(wk_h, wk_l, wv_h, wv_l, bk + l * EM, bv + l * EM);
        attn_m_k<<<dim3(NH, NCHUNK), 256>>>();
        nmat_k<<<dim3(NH, EM / 64), 256>>>(Wo + (size_t)l * EM * EM);

        // join: O-projection needs Q (single-term B = N)
        cudaStreamWaitEvent(0, evQ, 0);
        gemm_part1_k<<<gS, 256, SMEM_BYTES>>>(pqh, pnh, ppart, EM, EM, EM / 3);
        combine_ln_k<true><<<SQ, 256>>>(ppart, bo + l * EM, px, nullptr, phh,
                                        ln2_g + l * EM, ln2_b + l * EM);

        // join: first W1 use must wait for side-stream weight conversion
        if (l == 0) cudaStreamWaitEvent(0, evW, 0);
        gemm_w1<<<gF, 256, SMEM_BYTES>>>(phh, w1_h, b1 + l * FFD, pff, FFD, EM);

        // W2: split-K=3 single-term, combine + next LN fused
        gemm_part1_k<<<gS, 256, SMEM_BYTES>>>(pff, w2_h, ppart, EM, FFD, FFD / 3);
        if (l + 1 < NL) {
            combine_ln_k<true><<<SQ, 256>>>(ppart, b2 + l * EM, px, nullptr, phh,
                                            ln1_g + (l + 1) * EM, ln1_b + (l + 1) * EM);
        } else {
            combine_ln_k<false><<<SQ, 256>>>(ppart, b2 + l * EM, px, out, nullptr,
                                             lnf_g, lnf_b);
        }
    }
}

// round 17
// speedup vs baseline: 1.3899x; 1.0176x over previous
#include <cuda_runtime.h>
#include <cuda_fp16.h>
#include <math.h>
#include <stdint.h>

#define SQ   2048
#define EM   768
#define NH   12
#define DH   64
#define FFD  3072
#define NL   4
#define EPSF 1e-5f
#define NCHUNK 32

// GEMM tiling: BM=BN=128, BK=64 halves, 256 threads, warp tile 64x32
#define BM 128
#define BN 128
#define BK 64
#define RSTR 36            // smem row stride in u32 (32 used + 4 pad)
#define A_OFF 0
#define BH_OFF 4608
#define BL_OFF 9216
#define STAGE_U32 13824
#define SMEM_BYTES (2*STAGE_U32*4)   // 110592

// weight pool offsets (elements) — Wq,Wk,Wv,W1,W2 (Wo handled via N fusion)
#define WMAT   589824            // 768*768
#define W1MAT  2359296           // 768*3072
#define OFF_WQ 0
#define OFF_WK (4*WMAT)
#define OFF_WV (8*WMAT)
#define OFF_W1 (12*WMAT)
#define OFF_W2 (12*WMAT + 4*W1MAT)
#define WTOTAL (12*WMAT + 8*W1MAT)

// ---------------- scratch (no allocations allowed) ----------------
__device__ float g_x[SQ*EM];                 // residual stream (fp32)
__device__ float g_k[SQ*EM];                 // K (fp32)
__device__ float g_v[SQ*EM];                 // V (fp32)
__device__ float g_Mp[NH*NCHUNK*DH*DH];      // partial K^T V
__device__ float g_part[3*SQ*EM];            // split-K partials
__device__ __half g_qh[SQ*EM];               // Q (fp16)
__device__ __half g_h[SQ*EM];                // LN output (fp16)
__device__ __half g_ff[SQ*FFD];              // MLP hidden (fp16)
__device__ __half gwt_hi[WTOTAL];            // transposed weights hi
__device__ __half gwt_lo[WTOTAL];            // transposed weights lo (Q/K/V used)
__device__ __half g_nh[EM*EM];               // N = scale*M*Wo, transposed (fp16)

// ---------------- helpers ----------------
__device__ __forceinline__ void mma_fp16(float c[4], const uint32_t a[4], const uint32_t b[2]) {
    asm volatile(
        "mma.sync.aligned.m16n8k16.row.col.f32.f16.f16.f32 "
        "{%0,%1,%2,%3},{%4,%5,%6,%7},{%8,%9},{%0,%1,%2,%3};\n"
        : "+f"(c[0]), "+f"(c[1]), "+f"(c[2]), "+f"(c[3])
        : "r"(a[0]), "r"(a[1]), "r"(a[2]), "r"(a[3]), "r"(b[0]), "r"(b[1]));
}
__device__ __forceinline__ void cpa16(uint32_t dst, const void* src) {
    asm volatile("cp.async.cg.shared.global [%0], [%1], 16;\n" :: "r"(dst), "l"(src) : "memory");
}
__device__ __forceinline__ void cp_commit() { asm volatile("cp.async.commit_group;\n" ::: "memory"); }
__device__ __forceinline__ void cp_wait1()  { asm volatile("cp.async.wait_group 1;\n" ::: "memory"); }
__device__ __forceinline__ void cp_wait0()  { asm volatile("cp.async.wait_group 0;\n" ::: "memory"); }

__device__ __forceinline__ void split_fp16(float v, __half& hi, __half& lo) {
    hi = __float2half_rn(v);
    lo = __float2half_rn(v - __half2float(hi));
}

// ---------------- weight transpose + split: src[L][K][N] -> dst[L][N][K] (hi[,lo] fp16) ----------------
template<bool QKV>
__global__ void wconv_k(const float* __restrict__ s0, const float* __restrict__ s1,
                        const float* __restrict__ s2,
                        __half* __restrict__ dhi, __half* __restrict__ dlo,
                        int K, int N, int poolStride) {
    __shared__ float t[32][33];
    int m = 0, l = blockIdx.z;
    if (QKV) { m = blockIdx.z / NL; l = blockIdx.z % NL; }
    const float* src = (m == 0) ? s0 : (m == 1) ? s1 : s2;
    const size_t lofs = (size_t)l * K * N;
    const size_t dofs = (size_t)m * 4 * WMAT + (size_t)l * poolStride;
    const int n0 = blockIdx.x * 32, k0 = blockIdx.y * 32;
    const int tx = threadIdx.x, ty = threadIdx.y;
    #pragma unroll
    for (int i = 0; i < 4; i++)
        t[ty + 8*i][tx] = src[lofs + (size_t)(k0 + ty + 8*i) * N + n0 + tx];
    __syncthreads();
    const int u = tx & 15, nx = tx >> 4;
    #pragma unroll
    for (int i = 0; i < 2; i++) {
        int n = ty + 8*i + 16*nx;
        float v0 = t[2*u][n], v1 = t[2*u + 1][n];
        __half h0, l0, h1, l1;
        split_fp16(v0, h0, l0);
        split_fp16(v1, h1, l1);
        size_t o = dofs + (size_t)(n0 + n) * K + k0 + 2*u;
        *reinterpret_cast<__half2*>(dhi + o) = __halves2half2(h0, h1);
        if (QKV)   // lo kept for Q, K, V weights
            *reinterpret_cast<__half2*>(dlo + o) = __halves2half2(l0, l1);
    }
}

// ---------------- initial: x = emb + wpe, then LN -> fp16 ----------------
__global__ void __launch_bounds__(256)
addln_k(const float* __restrict__ emb, const float* __restrict__ wpe,
        float* __restrict__ px, __half* __restrict__ oh,
        const float* __restrict__ g, const float* __restrict__ b) {
    const int row = blockIdx.x;
    float loc[3];
    float s = 0.f, s2 = 0.f;
    #pragma unroll
    for (int t = 0; t < 3; t++) {
        int j = threadIdx.x + t * 256;
        size_t o = (size_t)row * EM + j;
        float v = emb[o] + wpe[o];
        px[o] = v;
        loc[t] = v;
        s += v; s2 += v * v;
    }
    __shared__ float rs[32], rs2[32];
    #pragma unroll
    for (int o = 16; o; o >>= 1) {
        s  += __shfl_down_sync(0xffffffffu, s,  o);
        s2 += __shfl_down_sync(0xffffffffu, s2, o);
    }
    int w = threadIdx.x >> 5, l = threadIdx.x & 31;
    if (l == 0) { rs[w] = s; rs2[w] = s2; }
    __syncthreads();
    if (w == 0) {
        s  = (l < 8) ? rs[l]  : 0.f;
        s2 = (l < 8) ? rs2[l] : 0.f;
        #pragma unroll
        for (int o = 4; o; o >>= 1) {
            s  += __shfl_down_sync(0xffffffffu, s,  o);
            s2 += __shfl_down_sync(0xffffffffu, s2, o);
        }
        if (l == 0) { rs[0] = s; rs2[0] = s2; }
    }
    __syncthreads();
    float mu  = rs[0] * (1.0f / EM);
    float var = rs2[0] * (1.0f / EM) - mu * mu;
    float inv = rsqrtf(var + EPSF);
    #pragma unroll
    for (int t = 0; t < 3; t++) {
        int j = threadIdx.x + t * 256;
        oh[(size_t)row * EM + j] = __float2half_rn((loc[t] - mu) * inv * g[j] + b[j]);
    }
}

// ---------------- combine 3 split-K partials + bias + residual, then LayerNorm ----------------
template<bool HALF>
__global__ void __launch_bounds__(256)
combine_ln_k(const float* __restrict__ parts, const float* __restrict__ bias,
             float* __restrict__ px, float* __restrict__ outf, __half* __restrict__ oh,
             const float* __restrict__ g, const float* __restrict__ b) {
    const int row = blockIdx.x;
    float loc[3];
    float s = 0.f, s2 = 0.f;
    #pragma unroll
    for (int t = 0; t < 3; t++) {
        int j = threadIdx.x + t * 256;
        size_t o = (size_t)row * EM + j;
        float v = px[o] + bias[j] + parts[o] + parts[o + (size_t)SQ*EM] + parts[o + 2*(size_t)SQ*EM];
        px[o] = v;
        loc[t] = v;
        s += v; s2 += v * v;
    }
    __shared__ float rs[32], rs2[32];
    #pragma unroll
    for (int o = 16; o; o >>= 1) {
        s  += __shfl_down_sync(0xffffffffu, s,  o);
        s2 += __shfl_down_sync(0xffffffffu, s2, o);
    }
    int w = threadIdx.x >> 5, l = threadIdx.x & 31;
    if (l == 0) { rs[w] = s; rs2[w] = s2; }
    __syncthreads();
    if (w == 0) {
        s  = (l < 8) ? rs[l]  : 0.f;
        s2 = (l < 8) ? rs2[l] : 0.f;
        #pragma unroll
        for (int o = 4; o; o >>= 1) {
            s  += __shfl_down_sync(0xffffffffu, s,  o);
            s2 += __shfl_down_sync(0xffffffffu, s2, o);
        }
        if (l == 0) { rs[0] = s; rs2[0] = s2; }
    }
    __syncthreads();
    float mu  = rs[0] * (1.0f / EM);
    float var = rs2[0] * (1.0f / EM) - mu * mu;
    float inv = rsqrtf(var + EPSF);
    #pragma unroll
    for (int t = 0; t < 3; t++) {
        int j = threadIdx.x + t * 256;
        float v = (loc[t] - mu) * inv * g[j] + b[j];
        if (HALF) oh[(size_t)row * EM + j] = __float2half_rn(v);
        else      outf[(size_t)row * EM + j] = v;
    }
}

// ---------------- fp16 tensor-core GEMM body (BK=64; TWOB: B hi+lo compensated) ----------------
template<bool GELU, bool RES, bool OHALF, bool PART, bool TWOB>
__device__ __forceinline__ void gemm_body(
    const __half* __restrict__ Ah,
    const __half* __restrict__ Bh, const __half* __restrict__ Bl,
    const float* __restrict__ bias, const float* __restrict__ res,
    float* __restrict__ C, __half* __restrict__ Ch,
    int N, int Kfull, int kbase, int kcount, int row0, int col0, uint32_t* smem)
{
    const int tid  = threadIdx.x;
    const int lane = tid & 31, warp = tid >> 5;
    const int wm = warp >> 2, wn = warp & 3;   // 2 x 4 warp grid
    const int g = lane >> 2, q = lane & 3;

    uint32_t sbase = (uint32_t)__cvta_generic_to_shared(smem);

    float acc[4][4][4];
    #pragma unroll
    for (int i = 0; i < 4; i++)
        #pragma unroll
        for (int j = 0; j < 4; j++)
            #pragma unroll
            for (int t = 0; t < 4; t++) acc[i][j][t] = 0.f;

    const int KT = kcount / BK;

    auto load_tile = [&](int kt, int st) {
        uint32_t base = sbase + st * STAGE_U32 * 4;
        #pragma unroll
        for (int t = 0; t < 4; t++) {
            int chunk = tid + t * 256;             // 0..1023
            int r = chunk >> 3, c4 = (chunk & 7) * 4;
            size_t aoff = (size_t)(row0 + r) * Kfull + kbase + kt * BK + (chunk & 7) * 8;
            cpa16(base + (uint32_t)(A_OFF + r * RSTR + c4) * 4, Ah + aoff);
            size_t boff = (size_t)(col0 + r) * Kfull + kbase + kt * BK + (chunk & 7) * 8;
            cpa16(base + (uint32_t)(BH_OFF + r * RSTR + c4) * 4, Bh + boff);
            if (TWOB)
                cpa16(base + (uint32_t)(BL_OFF + r * RSTR + c4) * 4, Bl + boff);
        }
        cp_commit();
    };

    load_tile(0, 0);
    for (int kt = 0; kt < KT; kt++) {
        if (kt + 1 < KT) { load_tile(kt + 1, (kt + 1) & 1); cp_wait1(); }
        else             { cp_wait0(); }
        __syncthreads();

        const uint32_t* S = smem + (kt & 1) * STAGE_U32;

        #pragma unroll
        for (int ks = 0; ks < 4; ks++) {
            const int kq = ks * 8 + q;
            uint32_t af[4][4], bh[4][2], bl[4][2];
            #pragma unroll
            for (int mi = 0; mi < 4; mi++) {
                int rb = (wm * 64 + mi * 16 + g) * RSTR + kq;
                af[mi][0] = S[A_OFF + rb];       af[mi][1] = S[A_OFF + rb + 8*RSTR];
                af[mi][2] = S[A_OFF + rb + 4];   af[mi][3] = S[A_OFF + rb + 8*RSTR + 4];
            }
            #pragma unroll
            for (int ni = 0; ni < 4; ni++) {
                int nb = (wn * 32 + ni * 8 + g) * RSTR + kq;
                bh[ni][0] = S[BH_OFF + nb];  bh[ni][1] = S[BH_OFF + nb + 4];
                if (TWOB) {
                    bl[ni][0] = S[BL_OFF + nb];  bl[ni][1] = S[BL_OFF + nb + 4];
                }
            }
            #pragma unroll
            for (int mi = 0; mi < 4; mi++)
                #pragma unroll
                for (int ni = 0; ni < 4; ni++) {
                    if (TWOB) mma_fp16(acc[mi][ni], af[mi], bl[ni]);
                    mma_fp16(acc[mi][ni], af[mi], bh[ni]);
                }
        }
        __syncthreads();
    }

    // epilogue (C layout: t0=(g,2q) t1=(g,2q+1) t2=(g+8,2q) t3=(g+8,2q+1))
    #pragma unroll
    for (int mi = 0; mi < 4; mi++) {
        #pragma unroll
        for (int ni = 0; ni < 4; ni++) {
            int r0 = row0 + wm * 64 + mi * 16 + g;
            int c0 = col0 + wn * 32 + ni * 8 + 2 * q;
            float bb0 = PART ? 0.f : bias[c0];
            float bb1 = PART ? 0.f : bias[c0 + 1];
            #pragma unroll
            for (int h = 0; h < 2; h++) {
                int r = r0 + h * 8;
                float v0 = acc[mi][ni][2 * h]     + bb0;
                float v1 = acc[mi][ni][2 * h + 1] + bb1;
                if (GELU) {
                    v0 = 0.5f * v0 * (1.0f + erff(v0 * 0.70710678118654752f));
                    v1 = 0.5f * v1 * (1.0f + erff(v1 * 0.70710678118654752f));
                }
                if (RES) {
                    v0 += res[(size_t)r * N + c0];
                    v1 += res[(size_t)r * N + c0 + 1];
                }
                if (OHALF) {
                    Ch[(size_t)r * N + c0]     = __float2half_rn(v0);
                    Ch[(size_t)r * N + c0 + 1] = __float2half_rn(v1);
                } else {
                    C[(size_t)r * N + c0]     = v0;
                    C[(size_t)r * N + c0 + 1] = v1;
                }
            }
        }
    }
}

// W1 column-group: single-B-term GEMM + GELU -> fp16; colBase selects 1024-col group
__global__ void __launch_bounds__(256, 2)
gemm_w1(const __half* __restrict__ Ah, const __half* __restrict__ Bh,
        const float* __restrict__ bias, __half* __restrict__ Ch,
        int N, int K, int colBase) {
    extern __shared__ uint32_t smem[];
    gemm_body<true, false, true, false, false>(Ah, Bh, nullptr, bias, nullptr, nullptr, Ch,
                                               N, K, 0, K, blockIdx.y * BM,
                                               colBase + blockIdx.x * BN, smem);
}

// split-K partial GEMM, single-term B; zidx selects the K range and output slice
__global__ void __launch_bounds__(256, 2)
gemm_part1_k(const __half* __restrict__ Ah, const __half* __restrict__ Bh,
             float* __restrict__ parts, int N, int Kfull, int ksplit, int zidx) {
    extern __shared__ uint32_t smem[];
    int z = (zidx < 0) ? blockIdx.z : zidx;
    float* Cp = parts + (size_t)z * SQ * N;
    gemm_body<false, false, false, true, false>(Ah, Bh, nullptr, nullptr, nullptr, Cp, nullptr,
                                                N, Kfull, z * ksplit, ksplit,
                                                blockIdx.y * BM, blockIdx.x * BN, smem);
}

// K+V projection: grid.x = 2 * (EM/BN); outputs fp32 K and V (2-term B)
__global__ void __launch_bounds__(256, 2)
kv_tc(const __half* __restrict__ Bk_hi, const __half* __restrict__ Bk_lo,
      const __half* __restrict__ Bv_hi, const __half* __restrict__ Bv_lo,
      const float* __restrict__ bk, const float* __restrict__ bv) {
    extern __shared__ uint32_t smem[];
    const int nb = EM / BN;   // 6
    int m = blockIdx.x / nb, cb = blockIdx.x % nb;
    const __half* Bh = (m == 0) ? Bk_hi : Bv_hi;
    const __half* Bl = (m == 0) ? Bk_lo : Bv_lo;
    const float*  b  = (m == 0) ? bk : bv;
    float*        C  = (m == 0) ? g_k : g_v;
    gemm_body<false, false, false, false, true>(g_h, Bh, Bl, b, nullptr, C, nullptr,
                                                EM, EM, 0, EM, blockIdx.y * BM, cb * BN, smem);
}

// Q projection (side stream, hidden): outputs fp16 Q (2-term B)
__global__ void __launch_bounds__(256, 2)
q_tc(const __half* __restrict__ Bq_hi, const __half* __restrict__ Bq_lo,
     const float* __restrict__ bq) {
    extern __shared__ uint32_t smem[];
    gemm_body<false, false, true, false, true>(g_h, Bq_hi, Bq_lo, bq, nullptr, nullptr, g_qh,
                                               EM, EM, 0, EM, blockIdx.y * BM, blockIdx.x * BN, smem);
}

// ---------------- attention part 1: partial M = K_h^T V_h over an S-chunk ----------------
__global__ void __launch_bounds__(256) attn_m_k() {
    const int h = blockIdx.x, chunk = blockIdx.y;
    __shared__ float Ks[32][65];
    __shared__ float Vs[32][65];
    const int tid = threadIdx.x;
    const int tx = tid & 15, ty = tid >> 4;
    float acc[4][4] = {};
    const int sbase = chunk * (SQ / NCHUNK);
    for (int s0 = 0; s0 < SQ / NCHUNK; s0 += 32) {
        #pragma unroll
        for (int i = 0; i < 2; i++) {
            int idx = tid + i * 256;            // 0..511 over 32 rows x 16 float4
            int r = idx >> 4, c4 = (idx & 15) * 4;
            size_t gofs = (size_t)(sbase + s0 + r) * EM + h * 64 + c4;
            float4 kv = *reinterpret_cast<const float4*>(g_k + gofs);
            Ks[r][c4] = kv.x; Ks[r][c4+1] = kv.y; Ks[r][c4+2] = kv.z; Ks[r][c4+3] = kv.w;
            float4 vv = *reinterpret_cast<const float4*>(g_v + gofs);
            Vs[r][c4] = vv.x; Vs[r][c4+1] = vv.y; Vs[r][c4+2] = vv.z; Vs[r][c4+3] = vv.w;
        }
        __syncthreads();
        #pragma unroll
        for (int ss = 0; ss < 32; ss++) {
            float a[4], bb[4];
            #pragma unroll
            for (int i = 0; i < 4; i++) a[i]  = Ks[ss][ty + i * 16];
            #pragma unroll
            for (int j = 0; j < 4; j++) bb[j] = Vs[ss][tx + j * 16];
            #pragma unroll
            for (int i = 0; i < 4; i++)
                #pragma unroll
                for (int j = 0; j < 4; j++)
                    acc[i][j] += a[i] * bb[j];
        }
        __syncthreads();
    }
    #pragma unroll
    for (int i = 0; i < 4; i++)
        #pragma unroll
        for (int j = 0; j < 4; j++)
            g_Mp[((h * NCHUNK + chunk) * 64 + ty + i * 16) * 64 + tx + j * 16] = acc[i][j];
}

// ---------------- N = scale * M * Wo  (per head, transposed fp16) ----------------
__global__ void __launch_bounds__(256) nmat_k(const float* __restrict__ Wo) {
    const int h = blockIdx.x, ob = blockIdx.y;
    __shared__ float Ms[64][65];
    __shared__ float Ws[64][65];
    const int tid = threadIdx.x;
    #pragma unroll
    for (int i = 0; i < 16; i++) {
        int idx = tid + i * 256;
        int d1 = idx >> 6, d2 = idx & 63;
        float s = 0.f;
        #pragma unroll
        for (int c = 0; c < NCHUNK; c++)
            s += g_Mp[((h * NCHUNK + c) * 64 + d1) * 64 + d2];
        Ms[d1][d2] = s * 0.125f;   // DH^-0.5
        int e = idx >> 6, o = idx & 63;
        Ws[e][o] = Wo[(size_t)(h * 64 + e) * EM + ob * 64 + o];
    }
    __syncthreads();
    const int o = tid & 63, dbase = (tid >> 6) * 16;
    #pragma unroll
    for (int dd = 0; dd < 16; dd++) {
        int d = dbase + dd;
        float s = 0.f;
        #pragma unroll
        for (int e = 0; e < 64; e++)
            s += Ms[d][e] * Ws[e][o];
        g_nh[(size_t)(ob * 64 + o) * EM + h * 64 + d] = __float2half_rn(s);
    }
}

// ---------------- host ----------------
extern "C" void kernel_launch(void* const* d_in, const int* in_sizes, int n_in,
                              void* d_out, int out_size) {
    const float* emb   = (const float*)d_in[0];
    const float* wpe   = (const float*)d_in[1];
    const float* ln1_g = (const float*)d_in[2];
    const float* ln1_b = (const float*)d_in[3];
    const float* Wq    = (const float*)d_in[4];
    const float* bq    = (const float*)d_in[5];
    const float* Wk    = (const float*)d_in[6];
    const float* bk    = (const float*)d_in[7];
    const float* Wv    = (const float*)d_in[8];
    const float* bv    = (const float*)d_in[9];
    const float* Wo    = (const float*)d_in[10];
    const float* bo    = (const float*)d_in[11];
    const float* ln2_g = (const float*)d_in[12];
    const float* ln2_b = (const float*)d_in[13];
    const float* W1    = (const float*)d_in[14];
    const float* b1    = (const float*)d_in[15];
    const float* W2    = (const float*)d_in[16];
    const float* b2    = (const float*)d_in[17];
    const float* lnf_g = (const float*)d_in[18];
    const float* lnf_b = (const float*)d_in[19];
    float* out = (float*)d_out;

    float *px, *ppart;
    __half *pwh, *pwl, *pnh, *pqh, *phh, *pff;
    cudaGetSymbolAddress((void**)&px,    g_x);
    cudaGetSymbolAddress((void**)&ppart, g_part);
    cudaGetSymbolAddress((void**)&pwh,   gwt_hi);
    cudaGetSymbolAddress((void**)&pwl,   gwt_lo);
    cudaGetSymbolAddress((void**)&pnh,   g_nh);
    cudaGetSymbolAddress((void**)&pqh,   g_qh);
    cudaGetSymbolAddress((void**)&phh,   g_h);
    cudaGetSymbolAddress((void**)&pff,   g_ff);

    cudaFuncSetAttribute(gemm_w1,
                         cudaFuncAttributeMaxDynamicSharedMemorySize, SMEM_BYTES);
    cudaFuncSetAttribute(gemm_part1_k,
                         cudaFuncAttributeMaxDynamicSharedMemorySize, SMEM_BYTES);
    cudaFuncSetAttribute(kv_tc,
                         cudaFuncAttributeMaxDynamicSharedMemorySize, SMEM_BYTES);
    cudaFuncSetAttribute(q_tc,
                         cudaFuncAttributeMaxDynamicSharedMemorySize, SMEM_BYTES);

    // streams + fork/join events (host objects; created once, no device memory)
    static cudaStream_t s2 = nullptr, s3 = nullptr;
    static cudaEvent_t evF = nullptr, evQ = nullptr, evW = nullptr;
    static cudaEvent_t evL2 = nullptr, evZ1 = nullptr, evZ2 = nullptr;
    if (!s2) {
        cudaStreamCreateWithFlags(&s2, cudaStreamNonBlocking);
        cudaStreamCreateWithFlags(&s3, cudaStreamNonBlocking);
        cudaEventCreateWithFlags(&evF,  cudaEventDisableTiming);
        cudaEventCreateWithFlags(&evQ,  cudaEventDisableTiming);
        cudaEventCreateWithFlags(&evW,  cudaEventDisableTiming);
        cudaEventCreateWithFlags(&evL2, cudaEventDisableTiming);
        cudaEventCreateWithFlags(&evZ1, cudaEventDisableTiming);
        cudaEventCreateWithFlags(&evZ2, cudaEventDisableTiming);
    }

    dim3 wblk(32, 8);

    // fork: W1/W2 weight conversion on side stream (hi only)
    cudaEventRecord(evF, 0);
    cudaStreamWaitEvent(s2, evF, 0);
    wconv_k<false><<<dim3(FFD/32, EM/32,  NL), wblk, 0, s2>>>(
        W1, nullptr, nullptr, pwh + OFF_W1, nullptr, EM,  FFD, W1MAT);
    wconv_k<false><<<dim3(EM/32,  FFD/32, NL), wblk, 0, s2>>>(
        W2, nullptr, nullptr, pwh + OFF_W2, nullptr, FFD, EM,  W1MAT);
    cudaEventRecord(evW, s2);

    // main stream: QKV weight conversion + initial add+LN
    wconv_k<true><<<dim3(EM/32, EM/32, 3*NL), wblk>>>(
        Wq, Wk, Wv, pwh + OFF_WQ, pwl + OFF_WQ, EM, EM, WMAT);
    addln_k<<<SQ, 256>>>(emb, wpe, px, phh, ln1_g, ln1_b);

    const dim3 gKV(2 * (EM / BN), SQ / BM);      // (12, 16)
    const dim3 gQ(EM / BN, SQ / BM);             // (6, 16)
    const dim3 gS(EM / BN, SQ / BM, 3);          // O-proj split-K (6, 16, 3)
    const dim3 gW1(FFD / BN / 3, SQ / BM);       // W1 column group (8, 16)
    const dim3 gW2(EM / BN, SQ / BM);            // W2 partial (6, 16)

    for (int l = 0; l < NL; l++) {
        const __half* wq_h = pwh + OFF_WQ + (size_t)l * WMAT;
        const __half* wq_l = pwl + OFF_WQ + (size_t)l * WMAT;
        const __half* wk_h = pwh + OFF_WK + (size_t)l * WMAT;
        const __half* wk_l = pwl + OFF_WK + (size_t)l * WMAT;
        const __half* wv_h = pwh + OFF_WV + (size_t)l * WMAT;
        const __half* wv_l = pwl + OFF_WV + (size_t)l * WMAT;
        const __half* w1_h = pwh + OFF_W1 + (size_t)l * W1MAT;
        const __half* w2_h = pwh + OFF_W2 + (size_t)l * W1MAT;

        // fork: Q projection (2-term, hidden) on side stream
        cudaEventRecord(evF, 0);
        cudaStreamWaitEvent(s2, evF, 0);
        q_tc<<<gQ, 256, SMEM_BYTES, s2>>>(wq_h, wq_l, bq + l * EM);
        cudaEventRecord(evQ, s2);

        kv_tc<<<gKV, 256, SMEM_BYTES>>>(wk_h, wk_l, wv_h, wv_l, bk + l * EM, bv + l * EM);
        attn_m_k<<<dim3(NH, NCHUNK), 256>>>();
        nmat_k<<<dim3(NH, EM / 64), 256>>>(Wo + (size_t)l * EM * EM);

        // join: O-projection needs Q (single-term B = N)
        cudaStreamWaitEvent(0, evQ, 0);
        gemm_part1_k<<<gS, 256, SMEM_BYTES>>>(pqh, pnh, ppart, EM, EM, EM / 3, -1);
        combine_ln_k<true><<<SQ, 256>>>(ppart, bo + l * EM, px, nullptr, phh,
                                        ln2_g + l * EM, ln2_b + l * EM);
        cudaEventRecord(evL2, 0);

        // W1/W2 pipelined across 3 streams: column group z of W1 feeds W2 partial z
        if (l == 0) cudaStreamWaitEvent(0, evW, 0);   // weights ready (s2 ordered naturally)
        cudaStreamWaitEvent(s2, evL2, 0);
        cudaStreamWaitEvent(s3, evL2, 0);
        if (l == 0) cudaStreamWaitEvent(s3, evW, 0);

        // z = 0 on main, z = 1 on s2, z = 2 on s3
        gemm_w1<<<gW1, 256, SMEM_BYTES>>>(phh, w1_h, b1 + l * FFD, pff, FFD, EM, 0);
        gemm_part1_k<<<gW2, 256, SMEM_BYTES>>>(pff, w2_h, ppart, EM, FFD, FFD / 3, 0);

        gemm_w1<<<gW1, 256, SMEM_BYTES, s2>>>(phh, w1_h, b1 + l * FFD, pff, FFD, EM, 1024);
        gemm_part1_k<<<gW2, 256, SMEM_BYTES, s2>>>(pff, w2_h, ppart, EM, FFD, FFD / 3, 1);
        cudaEventRecord(evZ1, s2);

        gemm_w1<<<gW1, 256, SMEM_BYTES, s3>>>(phh, w1_h, b1 + l * FFD, pff, FFD, EM, 2048);
        gemm_part1_k<<<gW2, 256, SMEM_BYTES, s3>>>(pff, w2_h, ppart, EM, FFD, FFD / 3, 2);
        cudaEventRecord(evZ2, s3);

        // join: combine needs all three W2 partials
        cudaStreamWaitEvent(0, evZ1, 0);
        cudaStreamWaitEvent(0, evZ2, 0);
        if (l + 1 < NL) {
            combine_ln_k<true><<<SQ, 256>>>(ppart, b2 + l * EM, px, nullptr, phh,
                                            ln1_g + (l + 1) * EM, ln1_b + (l + 1) * EM);
        } else {
            combine_ln_k<false><<<SQ, 256>>>(ppart, b2 + l * EM, px, out, nullptr,
                                             lnf_g, lnf_b);
        }
    }
}